// round 13
// baseline (speedup 1.0000x reference)
#include <cuda_runtime.h>
#include <cuda_bf16.h>
#include <cstdint>
#include <math.h>

#define PP 4
#define BB 128
#define DD 512
#define NN 32768
#define KKc 10
#define NT 256          // NN / 128 tiles
#define NEG_INF_F (-1e30f)
#define SIM_TH_F 0.7f
#define SCALE_F 10.0f

// ---------------- scratch (device globals) -----------------------------------
__device__ float g_invI[PP*BB];
__device__ float g_invT[PP*BB];
__device__ float g_fn2[PP*BB];
__device__ float g_img_sim[PP*BB*BB];
__device__ float g_txt_sim[PP*BB*BB];
__device__ int   g_valid[PP*BB];
__device__ float g_kl1[PP*BB];
__device__ float g_kl2[PP*BB];
__device__ float g_x[PP*BB];
__device__ float g_negsum[PP*BB];
__device__ float g_partial[PP*NT*BB];
__device__ uint32_t g_bits[2][PP*BB*4];   // per-row 128-bit >TH bitmaps (img, txt)

// ---------------- warp helpers ------------------------------------------------
__device__ __forceinline__ float warpSum(float v){
    #pragma unroll
    for (int o=16;o;o>>=1) v += __shfl_xor_sync(0xffffffffu, v, o);
    return v;
}
__device__ __forceinline__ float warpMax(float v){
    #pragma unroll
    for (int o=16;o;o>>=1) v = fmaxf(v, __shfl_xor_sync(0xffffffffu, v, o));
    return v;
}
__device__ float blockSum128(float v){
    __shared__ float sh[4];
    int w = threadIdx.x>>5, l = threadIdx.x&31;
    v = warpSum(v);
    __syncthreads();
    if (l==0) sh[w] = v;
    __syncthreads();
    return sh[0]+sh[1]+sh[2]+sh[3];
}
__device__ float blockMax128(float v){
    __shared__ float sh[4];
    int w = threadIdx.x>>5, l = threadIdx.x&31;
    v = warpMax(v);
    __syncthreads();
    if (l==0) sh[w] = v;
    __syncthreads();
    return fmaxf(fmaxf(sh[0],sh[1]), fmaxf(sh[2],sh[3]));
}
__device__ __forceinline__ uint32_t smem_u32(const void* p){
    uint32_t a;
    asm("{ .reg .u64 t; cvta.to.shared.u64 t, %1; cvt.u32.u64 %0, t; }" : "=r"(a) : "l"(p));
    return a;
}
__device__ __forceinline__ void ldsm_x4(uint32_t* r, uint32_t addr){
    asm volatile("ldmatrix.sync.aligned.m8n8.x4.shared.b16 {%0,%1,%2,%3}, [%4];"
                 : "=r"(r[0]), "=r"(r[1]), "=r"(r[2]), "=r"(r[3]) : "r"(addr));
}
__device__ __forceinline__ void mma_tf32(float* c, const uint32_t* a, const uint32_t* b){
    asm volatile("mma.sync.aligned.m16n8k8.row.col.f32.tf32.tf32.f32 "
                 "{%0,%1,%2,%3}, {%4,%5,%6,%7}, {%8,%9}, {%0,%1,%2,%3};"
                 : "+f"(c[0]), "+f"(c[1]), "+f"(c[2]), "+f"(c[3])
                 : "r"(a[0]), "r"(a[1]), "r"(a[2]), "r"(a[3]), "r"(b[0]), "r"(b[1]));
}
__device__ __forceinline__ void cpasync16(uint32_t dst, const void* src){
    asm volatile("cp.async.cg.shared.global [%0], [%1], 16;" :: "r"(dst), "l"(src));
}
#define CP_COMMIT() asm volatile("cp.async.commit_group;" ::: "memory")
#define CP_WAIT2()  asm volatile("cp.async.wait_group 2;" ::: "memory")

// ---------------- normalize ----------------------------------------------------
__global__ void normalize_kernel(const float* __restrict__ feature,
                                 const float* __restrict__ text_feature){
    int p = blockIdx.x / BB, b = blockIdx.x % BB;
    int tid = threadIdx.x;
    const float* f = feature + (size_t)(p*BB + b)*DD;
    const float* t = text_feature + (size_t)(b*PP + p)*DD;
    float sf = 0.f, st = 0.f;
    for (int d = tid; d < DD; d += 128){ float v=f[d]; sf += v*v; float w=t[d]; st += w*w; }
    __shared__ float sh[8];
    int w = tid>>5, l = tid&31;
    sf = warpSum(sf); st = warpSum(st);
    if (l==0){ sh[w]=sf; sh[4+w]=st; }
    __syncthreads();
    if (tid == 0){
        float fn2 = sh[0]+sh[1]+sh[2]+sh[3];
        float tn2 = sh[4]+sh[5]+sh[6]+sh[7];
        g_fn2[p*BB+b]  = fn2;
        g_invI[p*BB+b] = 1.f / fmaxf(sqrtf(fn2), 1e-12f);
        g_invT[p*BB+b] = 1.f / fmaxf(sqrtf(tn2), 1e-12f);
    }
}

// ---------------- mega kernel: neg GEMM + sim3 + pos + posvid -----------------
// bid <  1024            : neg tf32 HMMA tile (tile=bid&255, p=bid>>8)
// bid in [1024,1056)     : sim GEMM 32x128 tile (img or txt) + threshold bitmaps
// bid in [1056,1312)     : pos term, 2 rows per CTA
// bid in [1312,1317)     : pos_vid gather -> out[3..]
#define TSTRIDE 80                // bytes per row (16 floats + 4 pad)
#define TMAT (BB*TSTRIDE)         // 10240 B per matrix per stage
#define TSTG (2*TMAT)             // A+B per stage = 20480
#define NSTAGE 4
#define OFF_CN2  (NSTAGE*TSTG)    // 81920
#define OFF_MASK (OFF_CN2 + 512)
#define OFF_RED  (OFF_MASK + 512)
#define NEG_SMEM (OFF_RED + 1024) // 83968 B

__device__ __forceinline__ void issue_chunk_f32(const float* __restrict__ Ab,
                                                const float* __restrict__ Bb,
                                                uint32_t stageBase, int k, int tid){
    #pragma unroll
    for (int j = 0; j < 4; j++){
        int idx = j*256 + tid;
        int r = (idx >> 2) & 127, q = idx & 3;
        bool isA = idx < 512;
        const float* src = isA ? Ab + (size_t)r*DD + k*16 + q*4
                               : Bb + (size_t)r*DD + k*16 + q*4;
        uint32_t dst = stageBase + (isA ? 0 : TMAT) + r*TSTRIDE + q*16;
        cpasync16(dst, src);
    }
}

__global__ __launch_bounds__(256, 2) void mega_kernel(const float* __restrict__ feature,
                                                      const float* __restrict__ text,
                                                      const float* __restrict__ centers,
                                                      const int* __restrict__ cross_indices,
                                                      const int* __restrict__ position,
                                                      const int* __restrict__ vid,
                                                      float* __restrict__ out, int out_size){
    extern __shared__ __align__(16) char dsm[];
    const int bid = blockIdx.x;
    const int tid = threadIdx.x;

    if (bid < 1024){
        // ================= neg GEMM branch =====================
        const int p = bid >> 8;
        const int tile = bid & 255;
        const int n0g = tile * 128;
        const int wid = tid >> 5, lane = tid & 31;
        const int wm = wid >> 1, wn = wid & 1;

        float* s_cn2  = (float*)(dsm + OFF_CN2);
        float* s_mask = (float*)(dsm + OFF_MASK);
        float* s_red  = (float*)(dsm + OFF_RED);

        const float* Ab = feature + (size_t)p*BB*DD;
        const float* Bb = centers + ((size_t)p*NN + n0g)*DD;
        const uint32_t base = smem_u32(dsm);

        issue_chunk_f32(Ab, Bb, base + 0*TSTG, 0, tid); CP_COMMIT();
        issue_chunk_f32(Ab, Bb, base + 1*TSTG, 1, tid); CP_COMMIT();
        issue_chunk_f32(Ab, Bb, base + 2*TSTG, 2, tid); CP_COMMIT();

        if (tid < BB) s_mask[tid] = 1.f;
        __syncthreads();
        for (int i = tid; i < BB*KKc + BB; i += 256){
            int v = (i < BB*KKc) ? cross_indices[i] : position[i - BB*KKc];
            unsigned d = (unsigned)(v - n0g);
            if (d < 128u) s_mask[d] = 0.f;
        }

        float acc[2][8][4];
        #pragma unroll
        for (int i=0;i<2;i++)
            #pragma unroll
            for (int j=0;j<8;j++)
                #pragma unroll
                for (int e=0;e<4;e++) acc[i][j][e] = 0.f;

        // per-column squared norms from B fragment registers (exact fp32;
        // ldsm moves raw fp32 bits — tf32 truncation is MMA-internal only)
        float sq[8];
        #pragma unroll
        for (int t=0;t<8;t++) sq[t] = 0.f;

        const uint32_t aOff = (uint32_t)((((lane>>3)&1)*8 + (lane&7)) * TSTRIDE + (lane>>4)*16);
        const uint32_t bOff = (uint32_t)(((lane>>4)*8 + (lane&7)) * TSTRIDE + ((lane>>3)&1)*16);

        for (int c = 0; c < DD/16; c++){
            CP_WAIT2();
            __syncthreads();
            if (c + 3 < DD/16)
                issue_chunk_f32(Ab, Bb, base + ((c+3)&3)*TSTG, c+3, tid);
            CP_COMMIT();
            const uint32_t sAu = base + (c&3)*TSTG;
            const uint32_t sBu = sAu + TMAT;
            #pragma unroll
            for (int ks = 0; ks < 2; ks++){
                const uint32_t kb = ks*32;
                uint32_t a[2][4];
                #pragma unroll
                for (int i = 0; i < 2; i++)
                    ldsm_x4(a[i], sAu + (wm*32 + i*16)*TSTRIDE + aOff + kb);
                uint32_t b[4][4];
                #pragma unroll
                for (int j = 0; j < 4; j++)
                    ldsm_x4(b[j], sBu + (wn*64 + j*16)*TSTRIDE + bOff + kb);
                if (wid < 2){
                    #pragma unroll
                    for (int j = 0; j < 4; j++)
                        #pragma unroll
                        for (int r = 0; r < 4; r++){
                            float v = __uint_as_float(b[j][r]);
                            sq[j*2 + (r>>1)] += v*v;
                        }
                }
                #pragma unroll
                for (int i = 0; i < 2; i++)
                    #pragma unroll
                    for (int j = 0; j < 4; j++){
                        mma_tf32(acc[i][j*2],   a[i], &b[j][0]);
                        mma_tf32(acc[i][j*2+1], a[i], &b[j][2]);
                    }
            }
        }
        // cn2 reduce: lanes 4c..4c+3 hold k-partials of column c per n-tile t
        if (wid < 2){
            #pragma unroll
            for (int t = 0; t < 8; t++){
                float s = sq[t];
                s += __shfl_xor_sync(0xffffffffu, s, 1);
                s += __shfl_xor_sync(0xffffffffu, s, 2);
                if ((lane & 3) == 0)
                    s_cn2[wn*64 + t*8 + (lane>>2)] = s;
            }
        }
        __syncthreads();

        const int g = lane >> 2, tig = lane & 3;
        #pragma unroll
        for (int i = 0; i < 2; i++){
            int r0 = wm*32 + i*16 + g;
            int r1 = r0 + 8;
            float fn0 = g_fn2[p*BB + r0];
            float fn1 = g_fn2[p*BB + r1];
            float part0 = 0.f, part1 = 0.f;
            #pragma unroll
            for (int j = 0; j < 8; j++){
                int n = wn*64 + j*8 + tig*2;
                float mk0 = s_mask[n],   mk1 = s_mask[n+1];
                float cn0 = s_cn2[n],    cn1 = s_cn2[n+1];
                float d00 = fn0 + cn0 - 2.f*acc[i][j][0];
                float d01 = fn0 + cn1 - 2.f*acc[i][j][1];
                float d10 = fn1 + cn0 - 2.f*acc[i][j][2];
                float d11 = fn1 + cn1 - 2.f*acc[i][j][3];
                part0 += mk0*__expf(-SCALE_F*sqrtf(fmaxf(d00,1e-12f)))
                       + mk1*__expf(-SCALE_F*sqrtf(fmaxf(d01,1e-12f)));
                part1 += mk0*__expf(-SCALE_F*sqrtf(fmaxf(d10,1e-12f)))
                       + mk1*__expf(-SCALE_F*sqrtf(fmaxf(d11,1e-12f)));
            }
            part0 += __shfl_xor_sync(0xffffffffu, part0, 1);
            part0 += __shfl_xor_sync(0xffffffffu, part0, 2);
            part1 += __shfl_xor_sync(0xffffffffu, part1, 1);
            part1 += __shfl_xor_sync(0xffffffffu, part1, 2);
            if (tig == 0){
                s_red[r0*2 + wn] = part0;
                s_red[r1*2 + wn] = part1;
            }
        }
        __syncthreads();
        if (tid < BB)
            g_partial[((size_t)p*NT + tile)*BB + tid] = s_red[tid*2] + s_red[tid*2+1];

    } else if (bid < 1056){
        // ================= sim GEMM branch =========
        const int s = bid - 1024;
        const int p = s >> 3, rt = (s >> 1) & 3, mat = s & 1;
        const int tx = tid & 15, ty = tid >> 4;
        float (*sA)[36]  = (float(*)[36])dsm;                 //  4608 B
        float (*sB)[132] = (float(*)[132])(dsm + 4608);       // 16896 B
        uint32_t* sbits  = (uint32_t*)(dsm + 21504);          //   512 B
        const float* inv = (mat == 0) ? g_invI : g_invT;
        const int r0 = rt*32;

        if (tid < 128) sbits[tid] = 0;

        const int ar = tid >> 3, aq = tid & 7;
        const float invA = inv[p*BB + r0 + ar];
        const float* aPtr = (mat == 0)
            ? feature + (size_t)(p*BB + r0 + ar)*DD + aq*4
            : text    + (size_t)((r0 + ar)*PP + p)*DD + aq*4;
        float invB[4];
        const float* bPtr[4];
        #pragma unroll
        for (int it = 0; it < 4; it++){
            int idx = it*256 + tid;
            int br = idx >> 3, bq = idx & 7;
            invB[it] = inv[p*BB + br];
            bPtr[it] = (mat == 0)
                ? feature + (size_t)(p*BB + br)*DD + bq*4
                : text    + (size_t)(br*PP + p)*DD + bq*4;
        }

        float acc[2][8];
        #pragma unroll
        for (int i=0;i<2;i++)
            #pragma unroll
            for (int j=0;j<8;j++) acc[i][j] = 0.f;

        for (int k0 = 0; k0 < DD; k0 += 32){
            {
                float4 v = *(const float4*)(aPtr + k0);
                sA[aq*4+0][ar] = v.x*invA; sA[aq*4+1][ar] = v.y*invA;
                sA[aq*4+2][ar] = v.z*invA; sA[aq*4+3][ar] = v.w*invA;
            }
            #pragma unroll
            for (int it = 0; it < 4; it++){
                int idx = it*256 + tid;
                int br = idx >> 3, bq = idx & 7;
                float4 v = *(const float4*)(bPtr[it] + k0);
                float iv = invB[it];
                sB[bq*4+0][br] = v.x*iv; sB[bq*4+1][br] = v.y*iv;
                sB[bq*4+2][br] = v.z*iv; sB[bq*4+3][br] = v.w*iv;
            }
            __syncthreads();
            #pragma unroll
            for (int k = 0; k < 32; k++){
                float a0 = sA[k][ty], a1 = sA[k][ty+16];
                float4 b0 = *(const float4*)&sB[k][tx*8];
                float4 b1 = *(const float4*)&sB[k][tx*8+4];
                float bb[8] = {b0.x,b0.y,b0.z,b0.w,b1.x,b1.y,b1.z,b1.w};
                #pragma unroll
                for (int j = 0; j < 8; j++){
                    acc[0][j] += a0*bb[j];
                    acc[1][j] += a1*bb[j];
                }
            }
            __syncthreads();
        }

        float* osim = (mat == 0) ? g_img_sim : g_txt_sim;
        #pragma unroll
        for (int i = 0; i < 2; i++){
            int lrow = ty + i*16;
            int row = r0 + lrow;
            float o[8];
            #pragma unroll
            for (int j = 0; j < 8; j++) o[j] = acc[i][j]*2.f;   // / TEMP
            float* dst = osim + ((size_t)(p*BB + row))*BB + tx*8;
            *(float4*)dst     = make_float4(o[0],o[1],o[2],o[3]);
            *(float4*)(dst+4) = make_float4(o[4],o[5],o[6],o[7]);
            uint32_t byte = 0;
            #pragma unroll
            for (int j = 0; j < 8; j++) if (o[j] > SIM_TH_F) byte |= (1u << j);
            atomicOr(&sbits[lrow*4 + (tx>>2)], byte << ((tx&3)*8));
        }
        __syncthreads();
        if (tid < 128)
            g_bits[mat][(p*BB + r0 + (tid>>2))*4 + (tid&3)] = sbits[tid];

    } else if (bid < 1312){
        // ================= pos branch (2 rows per CTA) ========================
        const int pr = bid - 1056;
        const int half = tid >> 7;
        const int wg = (tid >> 5) & 3;
        const int lane = tid & 31;
        const int row = pr*2 + half;           // == p*BB + b
        const int b = row & 127;
        const int p = row >> 7;
        __shared__ float s_e2[2][12];
        const float* f = feature + (size_t)row*DD;
        float fn2 = g_fn2[row];
        for (int k = wg; k < KKc; k += 4){
            int idx = cross_indices[b*KKc + k];
            const float* cc = centers + ((size_t)p*NN + idx)*DD;
            float dot = 0.f, sqv = 0.f;
            #pragma unroll
            for (int j = 0; j < 4; j++){
                float4 cf = *(const float4*)(cc + j*128 + lane*4);
                float4 ff = *(const float4*)(f  + j*128 + lane*4);
                dot += ff.x*cf.x + ff.y*cf.y + ff.z*cf.z + ff.w*cf.w;
                sqv += cf.x*cf.x + cf.y*cf.y + cf.z*cf.z + cf.w*cf.w;
            }
            dot = warpSum(dot);
            sqv = warpSum(sqv);
            if (lane == 0){
                float pd2 = fn2 + sqv - 2.f*dot;
                s_e2[half][k] = expf(-SCALE_F * sqrtf(fmaxf(pd2, 1e-12f)));
            }
        }
        __syncthreads();
        if ((tid & 127) == 0){
            float ssum = 0.f;
            #pragma unroll
            for (int k = 0; k < KKc; k++) ssum += s_e2[half][k];
            g_x[row] = logf(ssum);
        }
    } else {
        // ================= pos_vid gather branch ==============================
        int i = (bid - 1312)*256 + tid;
        if (i < BB*KKc && (3 + i) < out_size)
            out[3 + i] = (float)vid[cross_indices[i]];
    }
}

// ---------------- kl + neg-sum reduce per row ---------------------------------
__global__ void kl_kernel(){
    int p = blockIdx.x / BB, b = blockIdx.x % BB;
    int c = threadIdx.x;
    __shared__ unsigned char svv[128];

    // fold g_partial reduction for this row (deterministic tree order)
    float nsv = g_partial[((size_t)p*NT + c)*BB + b]
              + g_partial[((size_t)p*NT + 128 + c)*BB + b];
    float ns = blockSum128(nsv);
    if (c == 0) g_negsum[p*BB + b] = ns;

    const uint32_t* ib = &g_bits[0][(p*BB + c)*4];
    const uint32_t* tb = &g_bits[1][(p*BB + c)*4];
    uint32_t m = (ib[0]&tb[0]) | (ib[1]&tb[1]) | (ib[2]&tb[2]) | (ib[3]&tb[3]);
    int colm = (m != 0);
    svv[c] = (unsigned char)colm;
    float is = g_img_sim[((size_t)(p*BB+b))*BB + c];
    float ts = g_txt_sim[((size_t)(p*BB+b))*BB + c];
    float il = colm ? is : NEG_INF_F;
    float tl = colm ? ts : NEG_INF_F;
    float mi = blockMax128(il);
    float sumi = blockSum128(expf(il - mi));
    float lsei = mi + logf(sumi);
    float mt = blockMax128(tl);
    float sumt = blockSum128(expf(tl - mt));
    float lset = mt + logf(sumt);
    float img_logp = il - lsei;
    float txt_logp = tl - lset;
    float k1 = colm ? expf(txt_logp) * (txt_logp - img_logp) : 0.f;
    float k2 = colm ? expf(img_logp) * (img_logp - txt_logp) : 0.f;
    float s1 = blockSum128(k1);
    float s2 = blockSum128(k2);
    if (c == 0){
        int rv = svv[b];
        g_valid[p*BB+b] = rv;
        g_kl1[p*BB+b] = rv ? s1 : 0.f;
        g_kl2[p*BB+b] = rv ? s2 : 0.f;
    }
}

// ---------------- final combine ------------------------------------------------
__global__ void final_kernel(float* __restrict__ out, int out_size){
    int b = threadIdx.x;
    float closs = 0.f;
    for (int p = 0; p < PP; p++){
        float ns = g_negsum[p*BB + b];
        float y = logf(ns);
        float v = y - g_x[p*BB + b];
        float s = blockSum128(v);
        float lp = s / (float)BB;
        if (isnan(lp)) lp = 0.f;
        closs += lp;
    }
    closs /= (float)PP;
    float aloss = 0.f;
    for (int p = 0; p < PP; p++){
        float nv = blockSum128((float)g_valid[p*BB + b]);
        float s1 = blockSum128(g_kl1[p*BB + b]);
        float s2 = blockSum128(g_kl2[p*BB + b]);
        float pp = 0.5f * (s1 + s2) / fmaxf(nv, 1.f);
        if (nv > 0.f) aloss += pp;
    }
    float klw = fmaxf(0.5f * (1.f - 1.f/60.f), 0.1f);
    float total = closs + klw * aloss;
    if (b == 0 && out_size >= 3){
        out[0] = total;
        out[1] = closs;
        out[2] = aloss;
    }
}

// ---------------- launch ------------------------------------------------------
extern "C" void kernel_launch(void* const* d_in, const int* in_sizes, int n_in,
                              void* d_out, int out_size){
    const float* feature       = (const float*)d_in[0];
    const float* text_feature  = (const float*)d_in[1];
    const float* centers       = (const float*)d_in[2];
    const int*   position      = (const int*)d_in[3];
    const int*   cross_indices = (const int*)d_in[4];
    const int*   vid           = (const int*)d_in[5];
    float* out = (float*)d_out;

    static bool attr_set = false;
    if (!attr_set){
        cudaFuncSetAttribute(mega_kernel, cudaFuncAttributeMaxDynamicSharedMemorySize, NEG_SMEM);
        attr_set = true;
    }

    normalize_kernel<<<PP*BB, 128>>>(feature, text_feature);                       // idx 0
    mega_kernel<<<1317, 256, NEG_SMEM>>>(feature, text_feature, centers,
                                         cross_indices, position, vid,
                                         out, out_size);                           // idx 1
    kl_kernel<<<PP*BB, 128>>>();                                                   // idx 2
    final_kernel<<<1, 128>>>(out, out_size);                                       // idx 3
}

// round 14
// speedup vs baseline: 1.5249x; 1.5249x over previous
#include <cuda_runtime.h>
#include <cuda_bf16.h>
#include <cstdint>
#include <math.h>

#define PP 4
#define BB 128
#define DD 512
#define NN 32768
#define KKc 10
#define NT 256          // NN / 128 tiles
#define NEG_INF_F (-1e30f)
#define SIM_TH_F 0.7f
#define SCALE_F 10.0f

// ---------------- scratch (device globals) -----------------------------------
__device__ float g_invI[PP*BB];
__device__ float g_invT[PP*BB];
__device__ float g_fn2[PP*BB];
__device__ float g_img_sim[PP*BB*BB];
__device__ float g_txt_sim[PP*BB*BB];
__device__ int   g_valid[PP*BB];
__device__ float g_kl1[PP*BB];
__device__ float g_kl2[PP*BB];
__device__ float g_x[PP*BB];
__device__ float g_negsum[PP*BB];
__device__ float g_partial[PP*NT*BB];
__device__ uint32_t g_bits[2][PP*BB*4];   // per-row 128-bit >TH bitmaps (img, txt)
__device__ int   g_ctr;                   // kl completion ticket counter

// ---------------- warp helpers ------------------------------------------------
__device__ __forceinline__ float warpSum(float v){
    #pragma unroll
    for (int o=16;o;o>>=1) v += __shfl_xor_sync(0xffffffffu, v, o);
    return v;
}
__device__ __forceinline__ float warpMax(float v){
    #pragma unroll
    for (int o=16;o;o>>=1) v = fmaxf(v, __shfl_xor_sync(0xffffffffu, v, o));
    return v;
}
__device__ float blockSum128(float v){
    __shared__ float sh[4];
    int w = threadIdx.x>>5, l = threadIdx.x&31;
    v = warpSum(v);
    __syncthreads();
    if (l==0) sh[w] = v;
    __syncthreads();
    return sh[0]+sh[1]+sh[2]+sh[3];
}
__device__ float blockMax128(float v){
    __shared__ float sh[4];
    int w = threadIdx.x>>5, l = threadIdx.x&31;
    v = warpMax(v);
    __syncthreads();
    if (l==0) sh[w] = v;
    __syncthreads();
    return fmaxf(fmaxf(sh[0],sh[1]), fmaxf(sh[2],sh[3]));
}
__device__ __forceinline__ uint32_t smem_u32(const void* p){
    uint32_t a;
    asm("{ .reg .u64 t; cvta.to.shared.u64 t, %1; cvt.u32.u64 %0, t; }" : "=r"(a) : "l"(p));
    return a;
}
__device__ __forceinline__ void ldsm_x4(uint32_t* r, uint32_t addr){
    asm volatile("ldmatrix.sync.aligned.m8n8.x4.shared.b16 {%0,%1,%2,%3}, [%4];"
                 : "=r"(r[0]), "=r"(r[1]), "=r"(r[2]), "=r"(r[3]) : "r"(addr));
}
__device__ __forceinline__ void mma_tf32(float* c, const uint32_t* a, const uint32_t* b){
    asm volatile("mma.sync.aligned.m16n8k8.row.col.f32.tf32.tf32.f32 "
                 "{%0,%1,%2,%3}, {%4,%5,%6,%7}, {%8,%9}, {%0,%1,%2,%3};"
                 : "+f"(c[0]), "+f"(c[1]), "+f"(c[2]), "+f"(c[3])
                 : "r"(a[0]), "r"(a[1]), "r"(a[2]), "r"(a[3]), "r"(b[0]), "r"(b[1]));
}
__device__ __forceinline__ void cpasync16(uint32_t dst, const void* src){
    asm volatile("cp.async.cg.shared.global [%0], [%1], 16;" :: "r"(dst), "l"(src));
}
#define CP_COMMIT() asm volatile("cp.async.commit_group;" ::: "memory")
#define CP_WAIT2()  asm volatile("cp.async.wait_group 2;" ::: "memory")

// ---------------- normalize (+ ticket reset) ----------------------------------
__global__ void normalize_kernel(const float* __restrict__ feature,
                                 const float* __restrict__ text_feature){
    int p = blockIdx.x / BB, b = blockIdx.x % BB;
    int tid = threadIdx.x;
    if (blockIdx.x == 0 && tid == 0) g_ctr = 0;
    const float* f = feature + (size_t)(p*BB + b)*DD;
    const float* t = text_feature + (size_t)(b*PP + p)*DD;
    float sf = 0.f, st = 0.f;
    for (int d = tid; d < DD; d += 128){ float v=f[d]; sf += v*v; float w=t[d]; st += w*w; }
    __shared__ float sh[8];
    int w = tid>>5, l = tid&31;
    sf = warpSum(sf); st = warpSum(st);
    if (l==0){ sh[w]=sf; sh[4+w]=st; }
    __syncthreads();
    if (tid == 0){
        float fn2 = sh[0]+sh[1]+sh[2]+sh[3];
        float tn2 = sh[4]+sh[5]+sh[6]+sh[7];
        g_fn2[p*BB+b]  = fn2;
        g_invI[p*BB+b] = 1.f / fmaxf(sqrtf(fn2), 1e-12f);
        g_invT[p*BB+b] = 1.f / fmaxf(sqrtf(tn2), 1e-12f);
    }
}

// ---------------- mega kernel: neg GEMM + sim3 + pos + posvid -----------------
// bid <  1024        : neg tf32 HMMA tile (tile=bid&255, p=bid>>8)  [R12 internals]
// bid in [1024,1056) : sim GEMM 32x128 tile (img or txt) + threshold bitmaps
// bid in [1056,1312) : pos term, 2 rows per CTA
// bid in [1312,1317) : pos_vid gather -> out[3..]
#define TSTRIDE 80                // bytes per row (16 floats + 4 pad)
#define TMAT (BB*TSTRIDE)         // 10240 B per matrix per stage
#define TSTG (2*TMAT)             // A+B per stage = 20480
#define NSTAGE 4
#define OFF_CN2  (NSTAGE*TSTG)    // 81920
#define OFF_MASK (OFF_CN2 + 512)
#define OFF_RED  (OFF_MASK + 512)
#define NEG_SMEM (OFF_RED + 1024) // 83968 B

__device__ __forceinline__ void issue_chunk_f32(const float* __restrict__ Ab,
                                                const float* __restrict__ Bb,
                                                uint32_t stageBase, int k, int tid){
    #pragma unroll
    for (int j = 0; j < 4; j++){
        int idx = j*256 + tid;
        int r = (idx >> 2) & 127, q = idx & 3;
        bool isA = idx < 512;
        const float* src = isA ? Ab + (size_t)r*DD + k*16 + q*4
                               : Bb + (size_t)r*DD + k*16 + q*4;
        uint32_t dst = stageBase + (isA ? 0 : TMAT) + r*TSTRIDE + q*16;
        cpasync16(dst, src);
    }
}

__global__ __launch_bounds__(256, 2) void mega_kernel(const float* __restrict__ feature,
                                                      const float* __restrict__ text,
                                                      const float* __restrict__ centers,
                                                      const int* __restrict__ cross_indices,
                                                      const int* __restrict__ position,
                                                      const int* __restrict__ vid,
                                                      float* __restrict__ out, int out_size){
    extern __shared__ __align__(16) char dsm[];
    const int bid = blockIdx.x;
    const int tid = threadIdx.x;

    if (bid < 1024){
        // ================= neg GEMM branch (R12 internals) ====================
        const int p = bid >> 8;
        const int tile = bid & 255;
        const int n0g = tile * 128;
        const int wid = tid >> 5, lane = tid & 31;
        const int wm = wid >> 1, wn = wid & 1;

        float* s_cn2  = (float*)(dsm + OFF_CN2);
        float* s_mask = (float*)(dsm + OFF_MASK);
        float* s_red  = (float*)(dsm + OFF_RED);

        const float* Ab = feature + (size_t)p*BB*DD;
        const float* Bb = centers + ((size_t)p*NN + n0g)*DD;
        const uint32_t base = smem_u32(dsm);

        issue_chunk_f32(Ab, Bb, base + 0*TSTG, 0, tid); CP_COMMIT();
        issue_chunk_f32(Ab, Bb, base + 1*TSTG, 1, tid); CP_COMMIT();
        issue_chunk_f32(Ab, Bb, base + 2*TSTG, 2, tid); CP_COMMIT();

        if (tid < BB) s_mask[tid] = 1.f;
        __syncthreads();
        for (int i = tid; i < BB*KKc + BB; i += 256){
            int v = (i < BB*KKc) ? cross_indices[i] : position[i - BB*KKc];
            unsigned d = (unsigned)(v - n0g);
            if (d < 128u) s_mask[d] = 0.f;
        }

        float acc[2][8][4];
        #pragma unroll
        for (int i=0;i<2;i++)
            #pragma unroll
            for (int j=0;j<8;j++)
                #pragma unroll
                for (int e=0;e<4;e++) acc[i][j][e] = 0.f;

        const uint32_t aOff = (uint32_t)((((lane>>3)&1)*8 + (lane&7)) * TSTRIDE + (lane>>4)*16);
        const uint32_t bOff = (uint32_t)(((lane>>4)*8 + (lane&7)) * TSTRIDE + ((lane>>3)&1)*16);

        const int r0c = tid >> 1, hc = tid & 1;
        float sqAcc = 0.f;

        for (int c = 0; c < DD/16; c++){
            CP_WAIT2();
            __syncthreads();
            if (c + 3 < DD/16)
                issue_chunk_f32(Ab, Bb, base + ((c+3)&3)*TSTG, c+3, tid);
            CP_COMMIT();
            const uint32_t sAu = base + (c&3)*TSTG;
            const uint32_t sBu = sAu + TMAT;
            #pragma unroll
            for (int ks = 0; ks < 2; ks++){
                const uint32_t kb = ks*32;
                uint32_t a[2][4];
                #pragma unroll
                for (int i = 0; i < 2; i++)
                    ldsm_x4(a[i], sAu + (wm*32 + i*16)*TSTRIDE + aOff + kb);
                uint32_t b[4][4];
                #pragma unroll
                for (int j = 0; j < 4; j++)
                    ldsm_x4(b[j], sBu + (wn*64 + j*16)*TSTRIDE + bOff + kb);
                #pragma unroll
                for (int i = 0; i < 2; i++)
                    #pragma unroll
                    for (int j = 0; j < 4; j++){
                        mma_tf32(acc[i][j*2],   a[i], &b[j][0]);
                        mma_tf32(acc[i][j*2+1], a[i], &b[j][2]);
                    }
            }
            {
                const float* brow = (const float*)(dsm + (c&3)*TSTG + TMAT + r0c*TSTRIDE + hc*32);
                float4 v0 = *(const float4*)brow;
                float4 v1 = *(const float4*)(brow + 4);
                sqAcc += v0.x*v0.x + v0.y*v0.y + v0.z*v0.z + v0.w*v0.w
                       + v1.x*v1.x + v1.y*v1.y + v1.z*v1.z + v1.w*v1.w;
            }
        }
        {
            float sq = sqAcc + __shfl_xor_sync(0xffffffffu, sqAcc, 1);
            if (hc == 0) s_cn2[r0c] = sq;
        }
        __syncthreads();

        const int g = lane >> 2, tig = lane & 3;
        #pragma unroll
        for (int i = 0; i < 2; i++){
            int r0 = wm*32 + i*16 + g;
            int r1 = r0 + 8;
            float fn0 = g_fn2[p*BB + r0];
            float fn1 = g_fn2[p*BB + r1];
            float part0 = 0.f, part1 = 0.f;
            #pragma unroll
            for (int j = 0; j < 8; j++){
                int n = wn*64 + j*8 + tig*2;
                float mk0 = s_mask[n],   mk1 = s_mask[n+1];
                float cn0 = s_cn2[n],    cn1 = s_cn2[n+1];
                float d00 = fn0 + cn0 - 2.f*acc[i][j][0];
                float d01 = fn0 + cn1 - 2.f*acc[i][j][1];
                float d10 = fn1 + cn0 - 2.f*acc[i][j][2];
                float d11 = fn1 + cn1 - 2.f*acc[i][j][3];
                part0 += mk0*__expf(-SCALE_F*sqrtf(fmaxf(d00,1e-12f)))
                       + mk1*__expf(-SCALE_F*sqrtf(fmaxf(d01,1e-12f)));
                part1 += mk0*__expf(-SCALE_F*sqrtf(fmaxf(d10,1e-12f)))
                       + mk1*__expf(-SCALE_F*sqrtf(fmaxf(d11,1e-12f)));
            }
            part0 += __shfl_xor_sync(0xffffffffu, part0, 1);
            part0 += __shfl_xor_sync(0xffffffffu, part0, 2);
            part1 += __shfl_xor_sync(0xffffffffu, part1, 1);
            part1 += __shfl_xor_sync(0xffffffffu, part1, 2);
            if (tig == 0){
                s_red[r0*2 + wn] = part0;
                s_red[r1*2 + wn] = part1;
            }
        }
        __syncthreads();
        if (tid < BB)
            g_partial[((size_t)p*NT + tile)*BB + tid] = s_red[tid*2] + s_red[tid*2+1];

    } else if (bid < 1056){
        // ================= sim GEMM branch ====================================
        const int s = bid - 1024;
        const int p = s >> 3, rt = (s >> 1) & 3, mat = s & 1;
        const int tx = tid & 15, ty = tid >> 4;
        float (*sA)[36]  = (float(*)[36])dsm;
        float (*sB)[132] = (float(*)[132])(dsm + 4608);
        uint32_t* sbits  = (uint32_t*)(dsm + 21504);
        const float* inv = (mat == 0) ? g_invI : g_invT;
        const int r0 = rt*32;

        if (tid < 128) sbits[tid] = 0;

        const int ar = tid >> 3, aq = tid & 7;
        const float invA = inv[p*BB + r0 + ar];
        const float* aPtr = (mat == 0)
            ? feature + (size_t)(p*BB + r0 + ar)*DD + aq*4
            : text    + (size_t)((r0 + ar)*PP + p)*DD + aq*4;
        float invB[4];
        const float* bPtr[4];
        #pragma unroll
        for (int it = 0; it < 4; it++){
            int idx = it*256 + tid;
            int br = idx >> 3, bq = idx & 7;
            invB[it] = inv[p*BB + br];
            bPtr[it] = (mat == 0)
                ? feature + (size_t)(p*BB + br)*DD + bq*4
                : text    + (size_t)(br*PP + p)*DD + bq*4;
        }

        float acc[2][8];
        #pragma unroll
        for (int i=0;i<2;i++)
            #pragma unroll
            for (int j=0;j<8;j++) acc[i][j] = 0.f;

        for (int k0 = 0; k0 < DD; k0 += 32){
            {
                float4 v = *(const float4*)(aPtr + k0);
                sA[aq*4+0][ar] = v.x*invA; sA[aq*4+1][ar] = v.y*invA;
                sA[aq*4+2][ar] = v.z*invA; sA[aq*4+3][ar] = v.w*invA;
            }
            #pragma unroll
            for (int it = 0; it < 4; it++){
                int idx = it*256 + tid;
                int br = idx >> 3, bq = idx & 7;
                float4 v = *(const float4*)(bPtr[it] + k0);
                float iv = invB[it];
                sB[bq*4+0][br] = v.x*iv; sB[bq*4+1][br] = v.y*iv;
                sB[bq*4+2][br] = v.z*iv; sB[bq*4+3][br] = v.w*iv;
            }
            __syncthreads();
            #pragma unroll
            for (int k = 0; k < 32; k++){
                float a0 = sA[k][ty], a1 = sA[k][ty+16];
                float4 b0 = *(const float4*)&sB[k][tx*8];
                float4 b1 = *(const float4*)&sB[k][tx*8+4];
                float bb[8] = {b0.x,b0.y,b0.z,b0.w,b1.x,b1.y,b1.z,b1.w};
                #pragma unroll
                for (int j = 0; j < 8; j++){
                    acc[0][j] += a0*bb[j];
                    acc[1][j] += a1*bb[j];
                }
            }
            __syncthreads();
        }

        float* osim = (mat == 0) ? g_img_sim : g_txt_sim;
        #pragma unroll
        for (int i = 0; i < 2; i++){
            int lrow = ty + i*16;
            int row = r0 + lrow;
            float o[8];
            #pragma unroll
            for (int j = 0; j < 8; j++) o[j] = acc[i][j]*2.f;   // / TEMP
            float* dst = osim + ((size_t)(p*BB + row))*BB + tx*8;
            *(float4*)dst     = make_float4(o[0],o[1],o[2],o[3]);
            *(float4*)(dst+4) = make_float4(o[4],o[5],o[6],o[7]);
            uint32_t byte = 0;
            #pragma unroll
            for (int j = 0; j < 8; j++) if (o[j] > SIM_TH_F) byte |= (1u << j);
            atomicOr(&sbits[lrow*4 + (tx>>2)], byte << ((tx&3)*8));
        }
        __syncthreads();
        if (tid < 128)
            g_bits[mat][(p*BB + r0 + (tid>>2))*4 + (tid&3)] = sbits[tid];

    } else if (bid < 1312){
        // ================= pos branch (2 rows per CTA) ========================
        const int pr = bid - 1056;
        const int half = tid >> 7;
        const int wg = (tid >> 5) & 3;
        const int lane = tid & 31;
        const int row = pr*2 + half;           // == p*BB + b
        const int b = row & 127;
        const int p = row >> 7;
        __shared__ float s_e2[2][12];
        const float* f = feature + (size_t)row*DD;
        float fn2 = g_fn2[row];
        for (int k = wg; k < KKc; k += 4){
            int idx = cross_indices[b*KKc + k];
            const float* cc = centers + ((size_t)p*NN + idx)*DD;
            float dot = 0.f, sqv = 0.f;
            #pragma unroll
            for (int j = 0; j < 4; j++){
                float4 cf = *(const float4*)(cc + j*128 + lane*4);
                float4 ff = *(const float4*)(f  + j*128 + lane*4);
                dot += ff.x*cf.x + ff.y*cf.y + ff.z*cf.z + ff.w*cf.w;
                sqv += cf.x*cf.x + cf.y*cf.y + cf.z*cf.z + cf.w*cf.w;
            }
            dot = warpSum(dot);
            sqv = warpSum(sqv);
            if (lane == 0){
                float pd2 = fn2 + sqv - 2.f*dot;
                s_e2[half][k] = expf(-SCALE_F * sqrtf(fmaxf(pd2, 1e-12f)));
            }
        }
        __syncthreads();
        if ((tid & 127) == 0){
            float ssum = 0.f;
            #pragma unroll
            for (int k = 0; k < KKc; k++) ssum += s_e2[half][k];
            g_x[row] = logf(ssum);
        }
    } else {
        // ================= pos_vid gather branch ==============================
        int i = (bid - 1312)*256 + tid;
        if (i < BB*KKc && (3 + i) < out_size)
            out[3 + i] = (float)vid[cross_indices[i]];
    }
}

// ---------------- kl + neg-sum reduce per row + last-CTA final ----------------
__global__ void kl_kernel(float* __restrict__ out, int out_size){
    int p = blockIdx.x / BB, b = blockIdx.x % BB;
    int c = threadIdx.x;
    __shared__ unsigned char svv[128];
    __shared__ int s_ticket;

    // fold g_partial reduction for this row (deterministic tree order)
    float nsv = g_partial[((size_t)p*NT + c)*BB + b]
              + g_partial[((size_t)p*NT + 128 + c)*BB + b];
    float ns = blockSum128(nsv);
    if (c == 0) g_negsum[p*BB + b] = ns;

    const uint32_t* ib = &g_bits[0][(p*BB + c)*4];
    const uint32_t* tb = &g_bits[1][(p*BB + c)*4];
    uint32_t m = (ib[0]&tb[0]) | (ib[1]&tb[1]) | (ib[2]&tb[2]) | (ib[3]&tb[3]);
    int colm = (m != 0);
    svv[c] = (unsigned char)colm;
    float is = g_img_sim[((size_t)(p*BB+b))*BB + c];
    float ts = g_txt_sim[((size_t)(p*BB+b))*BB + c];
    float il = colm ? is : NEG_INF_F;
    float tl = colm ? ts : NEG_INF_F;
    float mi = blockMax128(il);
    float sumi = blockSum128(expf(il - mi));
    float lsei = mi + logf(sumi);
    float mt = blockMax128(tl);
    float sumt = blockSum128(expf(tl - mt));
    float lset = mt + logf(sumt);
    float img_logp = il - lsei;
    float txt_logp = tl - lset;
    float k1 = colm ? expf(txt_logp) * (txt_logp - img_logp) : 0.f;
    float k2 = colm ? expf(img_logp) * (img_logp - txt_logp) : 0.f;
    float s1 = blockSum128(k1);
    float s2 = blockSum128(k2);
    if (c == 0){
        int rv = svv[b];
        g_valid[p*BB+b] = rv;
        g_kl1[p*BB+b] = rv ? s1 : 0.f;
        g_kl2[p*BB+b] = rv ? s2 : 0.f;
    }

    // last CTA computes the final scalars
    __threadfence();
    if (c == 0) s_ticket = atomicAdd(&g_ctr, 1);
    __syncthreads();
    if (s_ticket == PP*BB - 1){
        __threadfence();
        float closs = 0.f;
        for (int pp_ = 0; pp_ < PP; pp_++){
            float nsv2 = g_negsum[pp_*BB + c];
            float y = logf(nsv2);
            float v = y - g_x[pp_*BB + c];
            float s = blockSum128(v);
            float lp = s / (float)BB;
            if (isnan(lp)) lp = 0.f;
            closs += lp;
        }
        closs /= (float)PP;
        float aloss = 0.f;
        for (int pp_ = 0; pp_ < PP; pp_++){
            float nv = blockSum128((float)g_valid[pp_*BB + c]);
            float sa = blockSum128(g_kl1[pp_*BB + c]);
            float sb = blockSum128(g_kl2[pp_*BB + c]);
            float pq = 0.5f * (sa + sb) / fmaxf(nv, 1.f);
            if (nv > 0.f) aloss += pq;
        }
        float klw = fmaxf(0.5f * (1.f - 1.f/60.f), 0.1f);
        float total = closs + klw * aloss;
        if (c == 0 && out_size >= 3){
            out[0] = total;
            out[1] = closs;
            out[2] = aloss;
        }
    }
}

// ---------------- launch ------------------------------------------------------
extern "C" void kernel_launch(void* const* d_in, const int* in_sizes, int n_in,
                              void* d_out, int out_size){
    const float* feature       = (const float*)d_in[0];
    const float* text_feature  = (const float*)d_in[1];
    const float* centers       = (const float*)d_in[2];
    const int*   position      = (const int*)d_in[3];
    const int*   cross_indices = (const int*)d_in[4];
    const int*   vid           = (const int*)d_in[5];
    float* out = (float*)d_out;

    static bool attr_set = false;
    if (!attr_set){
        cudaFuncSetAttribute(mega_kernel, cudaFuncAttributeMaxDynamicSharedMemorySize, NEG_SMEM);
        attr_set = true;
    }

    normalize_kernel<<<PP*BB, 128>>>(feature, text_feature);                       // idx 0
    mega_kernel<<<1317, 256, NEG_SMEM>>>(feature, text_feature, centers,
                                         cross_indices, position, vid,
                                         out, out_size);                           // idx 1
    kl_kernel<<<PP*BB, 128>>>(out, out_size);                                      // idx 2
}

// round 15
// speedup vs baseline: 1.6079x; 1.0544x over previous
#include <cuda_runtime.h>
#include <cuda_bf16.h>
#include <cstdint>
#include <math.h>

#define PP 4
#define BB 128
#define DD 512
#define NN 32768
#define KKc 10
#define NT 256          // NN / 128 tiles
#define NEG_INF_F (-1e30f)
#define SIM_TH_F 0.7f
#define SCALE_F 10.0f

// ---------------- scratch (device globals) -----------------------------------
__device__ float g_invI[PP*BB];
__device__ float g_invT[PP*BB];
__device__ float g_fn2[PP*BB];
__device__ float g_img_sim[PP*BB*BB];
__device__ float g_txt_sim[PP*BB*BB];
__device__ int   g_valid[PP*BB];
__device__ float g_kl1[PP*BB];
__device__ float g_kl2[PP*BB];
__device__ float g_x[PP*BB];
__device__ float g_negsum[PP*BB];
__device__ float g_partial[PP*NT*BB];
__device__ uint32_t g_bits[2][PP*BB*4];   // per-row 128-bit >TH bitmaps (img, txt)

// ---------------- warp helpers ------------------------------------------------
__device__ __forceinline__ float warpSum(float v){
    #pragma unroll
    for (int o=16;o;o>>=1) v += __shfl_xor_sync(0xffffffffu, v, o);
    return v;
}
__device__ __forceinline__ float warpMax(float v){
    #pragma unroll
    for (int o=16;o;o>>=1) v = fmaxf(v, __shfl_xor_sync(0xffffffffu, v, o));
    return v;
}
__device__ float blockSum128(float v){
    __shared__ float sh[4];
    int w = threadIdx.x>>5, l = threadIdx.x&31;
    v = warpSum(v);
    __syncthreads();
    if (l==0) sh[w] = v;
    __syncthreads();
    return sh[0]+sh[1]+sh[2]+sh[3];
}
__device__ float blockMax128(float v){
    __shared__ float sh[4];
    int w = threadIdx.x>>5, l = threadIdx.x&31;
    v = warpMax(v);
    __syncthreads();
    if (l==0) sh[w] = v;
    __syncthreads();
    return fmaxf(fmaxf(sh[0],sh[1]), fmaxf(sh[2],sh[3]));
}
__device__ __forceinline__ uint32_t smem_u32(const void* p){
    uint32_t a;
    asm("{ .reg .u64 t; cvta.to.shared.u64 t, %1; cvt.u32.u64 %0, t; }" : "=r"(a) : "l"(p));
    return a;
}
__device__ __forceinline__ void ldsm_x4(uint32_t* r, uint32_t addr){
    asm volatile("ldmatrix.sync.aligned.m8n8.x4.shared.b16 {%0,%1,%2,%3}, [%4];"
                 : "=r"(r[0]), "=r"(r[1]), "=r"(r[2]), "=r"(r[3]) : "r"(addr));
}
__device__ __forceinline__ void mma_tf32(float* c, const uint32_t* a, const uint32_t* b){
    asm volatile("mma.sync.aligned.m16n8k8.row.col.f32.tf32.tf32.f32 "
                 "{%0,%1,%2,%3}, {%4,%5,%6,%7}, {%8,%9}, {%0,%1,%2,%3};"
                 : "+f"(c[0]), "+f"(c[1]), "+f"(c[2]), "+f"(c[3])
                 : "r"(a[0]), "r"(a[1]), "r"(a[2]), "r"(a[3]), "r"(b[0]), "r"(b[1]));
}
__device__ __forceinline__ void cpasync16(uint32_t dst, const void* src){
    asm volatile("cp.async.cg.shared.global [%0], [%1], 16;" :: "r"(dst), "l"(src));
}
#define CP_COMMIT() asm volatile("cp.async.commit_group;" ::: "memory")
#define CP_WAIT2()  asm volatile("cp.async.wait_group 2;" ::: "memory")

// ---------------- normalize ----------------------------------------------------
__global__ void normalize_kernel(const float* __restrict__ feature,
                                 const float* __restrict__ text_feature){
    int p = blockIdx.x / BB, b = blockIdx.x % BB;
    int tid = threadIdx.x;
    const float* f = feature + (size_t)(p*BB + b)*DD;
    const float* t = text_feature + (size_t)(b*PP + p)*DD;
    float sf = 0.f, st = 0.f;
    for (int d = tid; d < DD; d += 128){ float v=f[d]; sf += v*v; float w=t[d]; st += w*w; }
    __shared__ float sh[8];
    int w = tid>>5, l = tid&31;
    sf = warpSum(sf); st = warpSum(st);
    if (l==0){ sh[w]=sf; sh[4+w]=st; }
    __syncthreads();
    if (tid == 0){
        float fn2 = sh[0]+sh[1]+sh[2]+sh[3];
        float tn2 = sh[4]+sh[5]+sh[6]+sh[7];
        g_fn2[p*BB+b]  = fn2;
        g_invI[p*BB+b] = 1.f / fmaxf(sqrtf(fn2), 1e-12f);
        g_invT[p*BB+b] = 1.f / fmaxf(sqrtf(tn2), 1e-12f);
    }
}

// ---------------- mega kernel: neg GEMM + sim3 + pos + posvid -----------------
// bid <  1024        : neg tf32 HMMA tile (tile=bid&255, p=bid>>8)  [R12 internals]
// bid in [1024,1056) : sim GEMM 32x128 tile (img or txt) + threshold bitmaps
// bid in [1056,1312) : pos term, 2 rows per CTA
// bid in [1312,1317) : pos_vid gather -> out[3..]
#define TSTRIDE 80                // bytes per row (16 floats + 4 pad)
#define TMAT (BB*TSTRIDE)         // 10240 B per matrix per stage
#define TSTG (2*TMAT)             // A+B per stage = 20480
#define NSTAGE 4
#define OFF_CN2  (NSTAGE*TSTG)    // 81920
#define OFF_MASK (OFF_CN2 + 512)
#define OFF_RED  (OFF_MASK + 512)
#define NEG_SMEM (OFF_RED + 1024) // 83968 B

__device__ __forceinline__ void issue_chunk_f32(const float* __restrict__ Ab,
                                                const float* __restrict__ Bb,
                                                uint32_t stageBase, int k, int tid){
    #pragma unroll
    for (int j = 0; j < 4; j++){
        int idx = j*256 + tid;
        int r = (idx >> 2) & 127, q = idx & 3;
        bool isA = idx < 512;
        const float* src = isA ? Ab + (size_t)r*DD + k*16 + q*4
                               : Bb + (size_t)r*DD + k*16 + q*4;
        uint32_t dst = stageBase + (isA ? 0 : TMAT) + r*TSTRIDE + q*16;
        cpasync16(dst, src);
    }
}

__global__ __launch_bounds__(256, 2) void mega_kernel(const float* __restrict__ feature,
                                                      const float* __restrict__ text,
                                                      const float* __restrict__ centers,
                                                      const int* __restrict__ cross_indices,
                                                      const int* __restrict__ position,
                                                      const int* __restrict__ vid,
                                                      float* __restrict__ out, int out_size){
    extern __shared__ __align__(16) char dsm[];
    const int bid = blockIdx.x;
    const int tid = threadIdx.x;

    if (bid < 1024){
        // ================= neg GEMM branch (R12 internals) ====================
        const int p = bid >> 8;
        const int tile = bid & 255;
        const int n0g = tile * 128;
        const int wid = tid >> 5, lane = tid & 31;
        const int wm = wid >> 1, wn = wid & 1;

        float* s_cn2  = (float*)(dsm + OFF_CN2);
        float* s_mask = (float*)(dsm + OFF_MASK);
        float* s_red  = (float*)(dsm + OFF_RED);

        const float* Ab = feature + (size_t)p*BB*DD;
        const float* Bb = centers + ((size_t)p*NN + n0g)*DD;
        const uint32_t base = smem_u32(dsm);

        issue_chunk_f32(Ab, Bb, base + 0*TSTG, 0, tid); CP_COMMIT();
        issue_chunk_f32(Ab, Bb, base + 1*TSTG, 1, tid); CP_COMMIT();
        issue_chunk_f32(Ab, Bb, base + 2*TSTG, 2, tid); CP_COMMIT();

        if (tid < BB) s_mask[tid] = 1.f;
        __syncthreads();
        for (int i = tid; i < BB*KKc + BB; i += 256){
            int v = (i < BB*KKc) ? cross_indices[i] : position[i - BB*KKc];
            unsigned d = (unsigned)(v - n0g);
            if (d < 128u) s_mask[d] = 0.f;
        }

        float acc[2][8][4];
        #pragma unroll
        for (int i=0;i<2;i++)
            #pragma unroll
            for (int j=0;j<8;j++)
                #pragma unroll
                for (int e=0;e<4;e++) acc[i][j][e] = 0.f;

        const uint32_t aOff = (uint32_t)((((lane>>3)&1)*8 + (lane&7)) * TSTRIDE + (lane>>4)*16);
        const uint32_t bOff = (uint32_t)(((lane>>4)*8 + (lane&7)) * TSTRIDE + ((lane>>3)&1)*16);

        const int r0c = tid >> 1, hc = tid & 1;
        float sqAcc = 0.f;

        for (int c = 0; c < DD/16; c++){
            CP_WAIT2();
            __syncthreads();
            if (c + 3 < DD/16)
                issue_chunk_f32(Ab, Bb, base + ((c+3)&3)*TSTG, c+3, tid);
            CP_COMMIT();
            const uint32_t sAu = base + (c&3)*TSTG;
            const uint32_t sBu = sAu + TMAT;
            #pragma unroll
            for (int ks = 0; ks < 2; ks++){
                const uint32_t kb = ks*32;
                uint32_t a[2][4];
                #pragma unroll
                for (int i = 0; i < 2; i++)
                    ldsm_x4(a[i], sAu + (wm*32 + i*16)*TSTRIDE + aOff + kb);
                uint32_t b[4][4];
                #pragma unroll
                for (int j = 0; j < 4; j++)
                    ldsm_x4(b[j], sBu + (wn*64 + j*16)*TSTRIDE + bOff + kb);
                #pragma unroll
                for (int i = 0; i < 2; i++)
                    #pragma unroll
                    for (int j = 0; j < 4; j++){
                        mma_tf32(acc[i][j*2],   a[i], &b[j][0]);
                        mma_tf32(acc[i][j*2+1], a[i], &b[j][2]);
                    }
            }
            {
                const float* brow = (const float*)(dsm + (c&3)*TSTG + TMAT + r0c*TSTRIDE + hc*32);
                float4 v0 = *(const float4*)brow;
                float4 v1 = *(const float4*)(brow + 4);
                sqAcc += v0.x*v0.x + v0.y*v0.y + v0.z*v0.z + v0.w*v0.w
                       + v1.x*v1.x + v1.y*v1.y + v1.z*v1.z + v1.w*v1.w;
            }
        }
        {
            float sq = sqAcc + __shfl_xor_sync(0xffffffffu, sqAcc, 1);
            if (hc == 0) s_cn2[r0c] = sq;
        }
        __syncthreads();

        const int g = lane >> 2, tig = lane & 3;
        #pragma unroll
        for (int i = 0; i < 2; i++){
            int r0 = wm*32 + i*16 + g;
            int r1 = r0 + 8;
            float fn0 = g_fn2[p*BB + r0];
            float fn1 = g_fn2[p*BB + r1];
            float part0 = 0.f, part1 = 0.f;
            #pragma unroll
            for (int j = 0; j < 8; j++){
                int n = wn*64 + j*8 + tig*2;
                float mk0 = s_mask[n],   mk1 = s_mask[n+1];
                float cn0 = s_cn2[n],    cn1 = s_cn2[n+1];
                float d00 = fn0 + cn0 - 2.f*acc[i][j][0];
                float d01 = fn0 + cn1 - 2.f*acc[i][j][1];
                float d10 = fn1 + cn0 - 2.f*acc[i][j][2];
                float d11 = fn1 + cn1 - 2.f*acc[i][j][3];
                part0 += mk0*__expf(-SCALE_F*sqrtf(fmaxf(d00,1e-12f)))
                       + mk1*__expf(-SCALE_F*sqrtf(fmaxf(d01,1e-12f)));
                part1 += mk0*__expf(-SCALE_F*sqrtf(fmaxf(d10,1e-12f)))
                       + mk1*__expf(-SCALE_F*sqrtf(fmaxf(d11,1e-12f)));
            }
            part0 += __shfl_xor_sync(0xffffffffu, part0, 1);
            part0 += __shfl_xor_sync(0xffffffffu, part0, 2);
            part1 += __shfl_xor_sync(0xffffffffu, part1, 1);
            part1 += __shfl_xor_sync(0xffffffffu, part1, 2);
            if (tig == 0){
                s_red[r0*2 + wn] = part0;
                s_red[r1*2 + wn] = part1;
            }
        }
        __syncthreads();
        if (tid < BB)
            g_partial[((size_t)p*NT + tile)*BB + tid] = s_red[tid*2] + s_red[tid*2+1];

    } else if (bid < 1056){
        // ================= sim GEMM branch ====================================
        const int s = bid - 1024;
        const int p = s >> 3, rt = (s >> 1) & 3, mat = s & 1;
        const int tx = tid & 15, ty = tid >> 4;
        float (*sA)[36]  = (float(*)[36])dsm;
        float (*sB)[132] = (float(*)[132])(dsm + 4608);
        uint32_t* sbits  = (uint32_t*)(dsm + 21504);
        const float* inv = (mat == 0) ? g_invI : g_invT;
        const int r0 = rt*32;

        if (tid < 128) sbits[tid] = 0;

        const int ar = tid >> 3, aq = tid & 7;
        const float invA = inv[p*BB + r0 + ar];
        const float* aPtr = (mat == 0)
            ? feature + (size_t)(p*BB + r0 + ar)*DD + aq*4
            : text    + (size_t)((r0 + ar)*PP + p)*DD + aq*4;
        float invB[4];
        const float* bPtr[4];
        #pragma unroll
        for (int it = 0; it < 4; it++){
            int idx = it*256 + tid;
            int br = idx >> 3, bq = idx & 7;
            invB[it] = inv[p*BB + br];
            bPtr[it] = (mat == 0)
                ? feature + (size_t)(p*BB + br)*DD + bq*4
                : text    + (size_t)(br*PP + p)*DD + bq*4;
        }

        float acc[2][8];
        #pragma unroll
        for (int i=0;i<2;i++)
            #pragma unroll
            for (int j=0;j<8;j++) acc[i][j] = 0.f;

        for (int k0 = 0; k0 < DD; k0 += 32){
            {
                float4 v = *(const float4*)(aPtr + k0);
                sA[aq*4+0][ar] = v.x*invA; sA[aq*4+1][ar] = v.y*invA;
                sA[aq*4+2][ar] = v.z*invA; sA[aq*4+3][ar] = v.w*invA;
            }
            #pragma unroll
            for (int it = 0; it < 4; it++){
                int idx = it*256 + tid;
                int br = idx >> 3, bq = idx & 7;
                float4 v = *(const float4*)(bPtr[it] + k0);
                float iv = invB[it];
                sB[bq*4+0][br] = v.x*iv; sB[bq*4+1][br] = v.y*iv;
                sB[bq*4+2][br] = v.z*iv; sB[bq*4+3][br] = v.w*iv;
            }
            __syncthreads();
            #pragma unroll
            for (int k = 0; k < 32; k++){
                float a0 = sA[k][ty], a1 = sA[k][ty+16];
                float4 b0 = *(const float4*)&sB[k][tx*8];
                float4 b1 = *(const float4*)&sB[k][tx*8+4];
                float bb[8] = {b0.x,b0.y,b0.z,b0.w,b1.x,b1.y,b1.z,b1.w};
                #pragma unroll
                for (int j = 0; j < 8; j++){
                    acc[0][j] += a0*bb[j];
                    acc[1][j] += a1*bb[j];
                }
            }
            __syncthreads();
        }

        float* osim = (mat == 0) ? g_img_sim : g_txt_sim;
        #pragma unroll
        for (int i = 0; i < 2; i++){
            int lrow = ty + i*16;
            int row = r0 + lrow;
            float o[8];
            #pragma unroll
            for (int j = 0; j < 8; j++) o[j] = acc[i][j]*2.f;   // / TEMP
            float* dst = osim + ((size_t)(p*BB + row))*BB + tx*8;
            *(float4*)dst     = make_float4(o[0],o[1],o[2],o[3]);
            *(float4*)(dst+4) = make_float4(o[4],o[5],o[6],o[7]);
            uint32_t byte = 0;
            #pragma unroll
            for (int j = 0; j < 8; j++) if (o[j] > SIM_TH_F) byte |= (1u << j);
            atomicOr(&sbits[lrow*4 + (tx>>2)], byte << ((tx&3)*8));
        }
        __syncthreads();
        if (tid < 128)
            g_bits[mat][(p*BB + r0 + (tid>>2))*4 + (tid&3)] = sbits[tid];

    } else if (bid < 1312){
        // ================= pos branch (2 rows per CTA) ========================
        const int pr = bid - 1056;
        const int half = tid >> 7;
        const int wg = (tid >> 5) & 3;
        const int lane = tid & 31;
        const int row = pr*2 + half;           // == p*BB + b
        const int b = row & 127;
        const int p = row >> 7;
        __shared__ float s_e2[2][12];
        const float* f = feature + (size_t)row*DD;
        float fn2 = g_fn2[row];
        for (int k = wg; k < KKc; k += 4){
            int idx = cross_indices[b*KKc + k];
            const float* cc = centers + ((size_t)p*NN + idx)*DD;
            float dot = 0.f, sqv = 0.f;
            #pragma unroll
            for (int j = 0; j < 4; j++){
                float4 cf = *(const float4*)(cc + j*128 + lane*4);
                float4 ff = *(const float4*)(f  + j*128 + lane*4);
                dot += ff.x*cf.x + ff.y*cf.y + ff.z*cf.z + ff.w*cf.w;
                sqv += cf.x*cf.x + cf.y*cf.y + cf.z*cf.z + cf.w*cf.w;
            }
            dot = warpSum(dot);
            sqv = warpSum(sqv);
            if (lane == 0){
                float pd2 = fn2 + sqv - 2.f*dot;
                s_e2[half][k] = expf(-SCALE_F * sqrtf(fmaxf(pd2, 1e-12f)));
            }
        }
        __syncthreads();
        if ((tid & 127) == 0){
            float ssum = 0.f;
            #pragma unroll
            for (int k = 0; k < KKc; k++) ssum += s_e2[half][k];
            g_x[row] = logf(ssum);
        }
    } else {
        // ================= pos_vid gather branch ==============================
        int i = (bid - 1312)*256 + tid;
        if (i < BB*KKc && (3 + i) < out_size)
            out[3 + i] = (float)vid[cross_indices[i]];
    }
}

// ---------------- kl + neg-sum reduce per row ---------------------------------
__global__ void kl_kernel(){
    int p = blockIdx.x / BB, b = blockIdx.x % BB;
    int c = threadIdx.x;
    __shared__ unsigned char svv[128];

    // fold g_partial reduction for this row (deterministic tree order)
    float nsv = g_partial[((size_t)p*NT + c)*BB + b]
              + g_partial[((size_t)p*NT + 128 + c)*BB + b];
    float ns = blockSum128(nsv);
    if (c == 0) g_negsum[p*BB + b] = ns;

    const uint32_t* ib = &g_bits[0][(p*BB + c)*4];
    const uint32_t* tb = &g_bits[1][(p*BB + c)*4];
    uint32_t m = (ib[0]&tb[0]) | (ib[1]&tb[1]) | (ib[2]&tb[2]) | (ib[3]&tb[3]);
    int colm = (m != 0);
    svv[c] = (unsigned char)colm;
    float is = g_img_sim[((size_t)(p*BB+b))*BB + c];
    float ts = g_txt_sim[((size_t)(p*BB+b))*BB + c];
    float il = colm ? is : NEG_INF_F;
    float tl = colm ? ts : NEG_INF_F;
    float mi = blockMax128(il);
    float sumi = blockSum128(expf(il - mi));
    float lsei = mi + logf(sumi);
    float mt = blockMax128(tl);
    float sumt = blockSum128(expf(tl - mt));
    float lset = mt + logf(sumt);
    float img_logp = il - lsei;
    float txt_logp = tl - lset;
    float k1 = colm ? expf(txt_logp) * (txt_logp - img_logp) : 0.f;
    float k2 = colm ? expf(img_logp) * (img_logp - txt_logp) : 0.f;
    float s1 = blockSum128(k1);
    float s2 = blockSum128(k2);
    if (c == 0){
        int rv = svv[b];
        g_valid[p*BB+b] = rv;
        g_kl1[p*BB+b] = rv ? s1 : 0.f;
        g_kl2[p*BB+b] = rv ? s2 : 0.f;
    }
}

// ---------------- final combine: 512 threads, one per (p,b) -------------------
__global__ void final_kernel(float* __restrict__ out, int out_size){
    int tid = threadIdx.x;          // 0..511
    int p = tid >> 7;
    int row = tid;                  // == p*BB + b
    int w = (tid >> 5) & 3;         // warp-in-group
    int lane = tid & 31;

    __shared__ float rC[PP][4], rN[PP][4], r1[PP][4], r2[PP][4];
    __shared__ float resC[PP], resA[PP];

    // one coalesced load round
    float ns  = g_negsum[row];
    float xv  = g_x[row];
    float nvv = (float)g_valid[row];
    float k1v = g_kl1[row];
    float k2v = g_kl2[row];

    float v = logf(ns) - xv;
    float sC = warpSum(v);
    float sN = warpSum(nvv);
    float s1 = warpSum(k1v);
    float s2 = warpSum(k2v);
    if (lane == 0){
        rC[p][w] = sC; rN[p][w] = sN; r1[p][w] = s1; r2[p][w] = s2;
    }
    __syncthreads();
    if (tid < PP){
        float c4 = rC[tid][0]+rC[tid][1]+rC[tid][2]+rC[tid][3];
        float n4 = rN[tid][0]+rN[tid][1]+rN[tid][2]+rN[tid][3];
        float a4 = r1[tid][0]+r1[tid][1]+r1[tid][2]+r1[tid][3];
        float b4 = r2[tid][0]+r2[tid][1]+r2[tid][2]+r2[tid][3];
        float lp = c4 / (float)BB;
        if (isnan(lp)) lp = 0.f;
        resC[tid] = lp;
        float pq = 0.5f * (a4 + b4) / fmaxf(n4, 1.f);
        resA[tid] = (n4 > 0.f) ? pq : 0.f;
    }
    __syncthreads();
    if (tid == 0 && out_size >= 3){
        float closs = (resC[0]+resC[1]+resC[2]+resC[3]) / (float)PP;
        float aloss = resA[0]+resA[1]+resA[2]+resA[3];
        float klw = fmaxf(0.5f * (1.f - 1.f/60.f), 0.1f);
        out[0] = closs + klw * aloss;
        out[1] = closs;
        out[2] = aloss;
    }
}

// ---------------- launch ------------------------------------------------------
extern "C" void kernel_launch(void* const* d_in, const int* in_sizes, int n_in,
                              void* d_out, int out_size){
    const float* feature       = (const float*)d_in[0];
    const float* text_feature  = (const float*)d_in[1];
    const float* centers       = (const float*)d_in[2];
    const int*   position      = (const int*)d_in[3];
    const int*   cross_indices = (const int*)d_in[4];
    const int*   vid           = (const int*)d_in[5];
    float* out = (float*)d_out;

    static bool attr_set = false;
    if (!attr_set){
        cudaFuncSetAttribute(mega_kernel, cudaFuncAttributeMaxDynamicSharedMemorySize, NEG_SMEM);
        attr_set = true;
    }

    normalize_kernel<<<PP*BB, 128>>>(feature, text_feature);                       // idx 0
    mega_kernel<<<1317, 256, NEG_SMEM>>>(feature, text_feature, centers,
                                         cross_indices, position, vid,
                                         out, out_size);                           // idx 1
    kl_kernel<<<PP*BB, 128>>>();                                                   // idx 2
    final_kernel<<<1, 512>>>(out, out_size);                                       // idx 3
}

// round 16
// speedup vs baseline: 1.6454x; 1.0233x over previous
#include <cuda_runtime.h>
#include <cuda_bf16.h>
#include <cstdint>
#include <math.h>

#define PP 4
#define BB 128
#define DD 512
#define NN 32768
#define KKc 10
#define NT 256          // NN / 128 tiles
#define NEG_INF_F (-1e30f)
#define SIM_TH_F 0.7f
#define SCALE_F 10.0f

// mega grid layout: small work first (fills wave-1 slack), neg GEMM last
#define NB_SIM   32
#define NB_POS   256
#define NB_GATH  5
#define NB_SMALL (NB_SIM + NB_POS + NB_GATH)   // 293
#define NB_NEG   1024
#define NB_TOTAL (NB_SMALL + NB_NEG)           // 1317

// ---------------- scratch (device globals) -----------------------------------
__device__ float g_invI[PP*BB];
__device__ float g_invT[PP*BB];
__device__ float g_fn2[PP*BB];
__device__ float g_img_sim[PP*BB*BB];
__device__ float g_txt_sim[PP*BB*BB];
__device__ int   g_valid[PP*BB];
__device__ float g_kl1[PP*BB];
__device__ float g_kl2[PP*BB];
__device__ float g_x[PP*BB];
__device__ float g_negsum[PP*BB];
__device__ float g_partial[PP*NT*BB];
__device__ uint32_t g_bits[2][PP*BB*4];   // per-row 128-bit >TH bitmaps (img, txt)

// ---------------- warp helpers ------------------------------------------------
__device__ __forceinline__ float warpSum(float v){
    #pragma unroll
    for (int o=16;o;o>>=1) v += __shfl_xor_sync(0xffffffffu, v, o);
    return v;
}
__device__ __forceinline__ float warpMax(float v){
    #pragma unroll
    for (int o=16;o;o>>=1) v = fmaxf(v, __shfl_xor_sync(0xffffffffu, v, o));
    return v;
}
__device__ float blockSum128(float v){
    __shared__ float sh[4];
    int w = threadIdx.x>>5, l = threadIdx.x&31;
    v = warpSum(v);
    __syncthreads();
    if (l==0) sh[w] = v;
    __syncthreads();
    return sh[0]+sh[1]+sh[2]+sh[3];
}
__device__ float blockMax128(float v){
    __shared__ float sh[4];
    int w = threadIdx.x>>5, l = threadIdx.x&31;
    v = warpMax(v);
    __syncthreads();
    if (l==0) sh[w] = v;
    __syncthreads();
    return fmaxf(fmaxf(sh[0],sh[1]), fmaxf(sh[2],sh[3]));
}
__device__ __forceinline__ uint32_t smem_u32(const void* p){
    uint32_t a;
    asm("{ .reg .u64 t; cvta.to.shared.u64 t, %1; cvt.u32.u64 %0, t; }" : "=r"(a) : "l"(p));
    return a;
}
__device__ __forceinline__ void ldsm_x4(uint32_t* r, uint32_t addr){
    asm volatile("ldmatrix.sync.aligned.m8n8.x4.shared.b16 {%0,%1,%2,%3}, [%4];"
                 : "=r"(r[0]), "=r"(r[1]), "=r"(r[2]), "=r"(r[3]) : "r"(addr));
}
__device__ __forceinline__ void mma_tf32(float* c, const uint32_t* a, const uint32_t* b){
    asm volatile("mma.sync.aligned.m16n8k8.row.col.f32.tf32.tf32.f32 "
                 "{%0,%1,%2,%3}, {%4,%5,%6,%7}, {%8,%9}, {%0,%1,%2,%3};"
                 : "+f"(c[0]), "+f"(c[1]), "+f"(c[2]), "+f"(c[3])
                 : "r"(a[0]), "r"(a[1]), "r"(a[2]), "r"(a[3]), "r"(b[0]), "r"(b[1]));
}
__device__ __forceinline__ void cpasync16(uint32_t dst, const void* src){
    asm volatile("cp.async.cg.shared.global [%0], [%1], 16;" :: "r"(dst), "l"(src));
}
#define CP_COMMIT() asm volatile("cp.async.commit_group;" ::: "memory")
#define CP_WAIT2()  asm volatile("cp.async.wait_group 2;" ::: "memory")

// ---------------- normalize ----------------------------------------------------
__global__ void normalize_kernel(const float* __restrict__ feature,
                                 const float* __restrict__ text_feature){
    int p = blockIdx.x / BB, b = blockIdx.x % BB;
    int tid = threadIdx.x;
    const float* f = feature + (size_t)(p*BB + b)*DD;
    const float* t = text_feature + (size_t)(b*PP + p)*DD;
    float sf = 0.f, st = 0.f;
    for (int d = tid; d < DD; d += 128){ float v=f[d]; sf += v*v; float w=t[d]; st += w*w; }
    __shared__ float sh[8];
    int w = tid>>5, l = tid&31;
    sf = warpSum(sf); st = warpSum(st);
    if (l==0){ sh[w]=sf; sh[4+w]=st; }
    __syncthreads();
    if (tid == 0){
        float fn2 = sh[0]+sh[1]+sh[2]+sh[3];
        float tn2 = sh[4]+sh[5]+sh[6]+sh[7];
        g_fn2[p*BB+b]  = fn2;
        g_invI[p*BB+b] = 1.f / fmaxf(sqrtf(fn2), 1e-12f);
        g_invT[p*BB+b] = 1.f / fmaxf(sqrtf(tn2), 1e-12f);
    }
}

// ---------------- mega kernel: sim + pos + posvid + neg GEMM ------------------
// bid <  32          : sim GEMM 32x128 tile (img or txt) + threshold bitmaps
// bid in [32,288)    : pos term, 2 rows per CTA
// bid in [288,293)   : pos_vid gather -> out[3..]
// bid in [293,1317)  : neg tf32 HMMA tile (R12 internals; scheduled last so the
//                      kernel tail is pure GEMM and small work fills wave-1 slack)
#define TSTRIDE 80                // bytes per row (16 floats + 4 pad)
#define TMAT (BB*TSTRIDE)         // 10240 B per matrix per stage
#define TSTG (2*TMAT)             // A+B per stage = 20480
#define NSTAGE 4
#define OFF_CN2  (NSTAGE*TSTG)    // 81920
#define OFF_MASK (OFF_CN2 + 512)
#define OFF_RED  (OFF_MASK + 512)
#define NEG_SMEM (OFF_RED + 1024) // 83968 B

__device__ __forceinline__ void issue_chunk_f32(const float* __restrict__ Ab,
                                                const float* __restrict__ Bb,
                                                uint32_t stageBase, int k, int tid){
    #pragma unroll
    for (int j = 0; j < 4; j++){
        int idx = j*256 + tid;
        int r = (idx >> 2) & 127, q = idx & 3;
        bool isA = idx < 512;
        const float* src = isA ? Ab + (size_t)r*DD + k*16 + q*4
                               : Bb + (size_t)r*DD + k*16 + q*4;
        uint32_t dst = stageBase + (isA ? 0 : TMAT) + r*TSTRIDE + q*16;
        cpasync16(dst, src);
    }
}

__global__ __launch_bounds__(256, 2) void mega_kernel(const float* __restrict__ feature,
                                                      const float* __restrict__ text,
                                                      const float* __restrict__ centers,
                                                      const int* __restrict__ cross_indices,
                                                      const int* __restrict__ position,
                                                      const int* __restrict__ vid,
                                                      float* __restrict__ out, int out_size){
    extern __shared__ __align__(16) char dsm[];
    const int bid = blockIdx.x;
    const int tid = threadIdx.x;

    if (bid >= NB_SMALL){
        // ================= neg GEMM branch (R12 internals) ====================
        const int t2 = bid - NB_SMALL;
        const int p = t2 >> 8;
        const int tile = t2 & 255;
        const int n0g = tile * 128;
        const int wid = tid >> 5, lane = tid & 31;
        const int wm = wid >> 1, wn = wid & 1;

        float* s_cn2  = (float*)(dsm + OFF_CN2);
        float* s_mask = (float*)(dsm + OFF_MASK);
        float* s_red  = (float*)(dsm + OFF_RED);

        const float* Ab = feature + (size_t)p*BB*DD;
        const float* Bb = centers + ((size_t)p*NN + n0g)*DD;
        const uint32_t base = smem_u32(dsm);

        issue_chunk_f32(Ab, Bb, base + 0*TSTG, 0, tid); CP_COMMIT();
        issue_chunk_f32(Ab, Bb, base + 1*TSTG, 1, tid); CP_COMMIT();
        issue_chunk_f32(Ab, Bb, base + 2*TSTG, 2, tid); CP_COMMIT();

        if (tid < BB) s_mask[tid] = 1.f;
        __syncthreads();
        for (int i = tid; i < BB*KKc + BB; i += 256){
            int v = (i < BB*KKc) ? cross_indices[i] : position[i - BB*KKc];
            unsigned d = (unsigned)(v - n0g);
            if (d < 128u) s_mask[d] = 0.f;
        }

        float acc[2][8][4];
        #pragma unroll
        for (int i=0;i<2;i++)
            #pragma unroll
            for (int j=0;j<8;j++)
                #pragma unroll
                for (int e=0;e<4;e++) acc[i][j][e] = 0.f;

        const uint32_t aOff = (uint32_t)((((lane>>3)&1)*8 + (lane&7)) * TSTRIDE + (lane>>4)*16);
        const uint32_t bOff = (uint32_t)(((lane>>4)*8 + (lane&7)) * TSTRIDE + ((lane>>3)&1)*16);

        const int r0c = tid >> 1, hc = tid & 1;
        float sqAcc = 0.f;

        for (int c = 0; c < DD/16; c++){
            CP_WAIT2();
            __syncthreads();
            if (c + 3 < DD/16)
                issue_chunk_f32(Ab, Bb, base + ((c+3)&3)*TSTG, c+3, tid);
            CP_COMMIT();
            const uint32_t sAu = base + (c&3)*TSTG;
            const uint32_t sBu = sAu + TMAT;
            #pragma unroll
            for (int ks = 0; ks < 2; ks++){
                const uint32_t kb = ks*32;
                uint32_t a[2][4];
                #pragma unroll
                for (int i = 0; i < 2; i++)
                    ldsm_x4(a[i], sAu + (wm*32 + i*16)*TSTRIDE + aOff + kb);
                uint32_t b[4][4];
                #pragma unroll
                for (int j = 0; j < 4; j++)
                    ldsm_x4(b[j], sBu + (wn*64 + j*16)*TSTRIDE + bOff + kb);
                #pragma unroll
                for (int i = 0; i < 2; i++)
                    #pragma unroll
                    for (int j = 0; j < 4; j++){
                        mma_tf32(acc[i][j*2],   a[i], &b[j][0]);
                        mma_tf32(acc[i][j*2+1], a[i], &b[j][2]);
                    }
            }
            {
                const float* brow = (const float*)(dsm + (c&3)*TSTG + TMAT + r0c*TSTRIDE + hc*32);
                float4 v0 = *(const float4*)brow;
                float4 v1 = *(const float4*)(brow + 4);
                sqAcc += v0.x*v0.x + v0.y*v0.y + v0.z*v0.z + v0.w*v0.w
                       + v1.x*v1.x + v1.y*v1.y + v1.z*v1.z + v1.w*v1.w;
            }
        }
        {
            float sq = sqAcc + __shfl_xor_sync(0xffffffffu, sqAcc, 1);
            if (hc == 0) s_cn2[r0c] = sq;
        }
        __syncthreads();

        const int g = lane >> 2, tig = lane & 3;
        #pragma unroll
        for (int i = 0; i < 2; i++){
            int r0 = wm*32 + i*16 + g;
            int r1 = r0 + 8;
            float fn0 = g_fn2[p*BB + r0];
            float fn1 = g_fn2[p*BB + r1];
            float part0 = 0.f, part1 = 0.f;
            #pragma unroll
            for (int j = 0; j < 8; j++){
                int n = wn*64 + j*8 + tig*2;
                float mk0 = s_mask[n],   mk1 = s_mask[n+1];
                float cn0 = s_cn2[n],    cn1 = s_cn2[n+1];
                float d00 = fn0 + cn0 - 2.f*acc[i][j][0];
                float d01 = fn0 + cn1 - 2.f*acc[i][j][1];
                float d10 = fn1 + cn0 - 2.f*acc[i][j][2];
                float d11 = fn1 + cn1 - 2.f*acc[i][j][3];
                part0 += mk0*__expf(-SCALE_F*sqrtf(fmaxf(d00,1e-12f)))
                       + mk1*__expf(-SCALE_F*sqrtf(fmaxf(d01,1e-12f)));
                part1 += mk0*__expf(-SCALE_F*sqrtf(fmaxf(d10,1e-12f)))
                       + mk1*__expf(-SCALE_F*sqrtf(fmaxf(d11,1e-12f)));
            }
            part0 += __shfl_xor_sync(0xffffffffu, part0, 1);
            part0 += __shfl_xor_sync(0xffffffffu, part0, 2);
            part1 += __shfl_xor_sync(0xffffffffu, part1, 1);
            part1 += __shfl_xor_sync(0xffffffffu, part1, 2);
            if (tig == 0){
                s_red[r0*2 + wn] = part0;
                s_red[r1*2 + wn] = part1;
            }
        }
        __syncthreads();
        if (tid < BB)
            g_partial[((size_t)p*NT + tile)*BB + tid] = s_red[tid*2] + s_red[tid*2+1];

    } else if (bid < NB_SIM){
        // ================= sim GEMM branch ====================================
        const int s = bid;
        const int p = s >> 3, rt = (s >> 1) & 3, mat = s & 1;
        const int tx = tid & 15, ty = tid >> 4;
        float (*sA)[36]  = (float(*)[36])dsm;
        float (*sB)[132] = (float(*)[132])(dsm + 4608);
        uint32_t* sbits  = (uint32_t*)(dsm + 21504);
        const float* inv = (mat == 0) ? g_invI : g_invT;
        const int r0 = rt*32;

        if (tid < 128) sbits[tid] = 0;

        const int ar = tid >> 3, aq = tid & 7;
        const float invA = inv[p*BB + r0 + ar];
        const float* aPtr = (mat == 0)
            ? feature + (size_t)(p*BB + r0 + ar)*DD + aq*4
            : text    + (size_t)((r0 + ar)*PP + p)*DD + aq*4;
        float invB[4];
        const float* bPtr[4];
        #pragma unroll
        for (int it = 0; it < 4; it++){
            int idx = it*256 + tid;
            int br = idx >> 3, bq = idx & 7;
            invB[it] = inv[p*BB + br];
            bPtr[it] = (mat == 0)
                ? feature + (size_t)(p*BB + br)*DD + bq*4
                : text    + (size_t)(br*PP + p)*DD + bq*4;
        }

        float acc[2][8];
        #pragma unroll
        for (int i=0;i<2;i++)
            #pragma unroll
            for (int j=0;j<8;j++) acc[i][j] = 0.f;

        for (int k0 = 0; k0 < DD; k0 += 32){
            {
                float4 v = *(const float4*)(aPtr + k0);
                sA[aq*4+0][ar] = v.x*invA; sA[aq*4+1][ar] = v.y*invA;
                sA[aq*4+2][ar] = v.z*invA; sA[aq*4+3][ar] = v.w*invA;
            }
            #pragma unroll
            for (int it = 0; it < 4; it++){
                int idx = it*256 + tid;
                int br = idx >> 3, bq = idx & 7;
                float4 v = *(const float4*)(bPtr[it] + k0);
                float iv = invB[it];
                sB[bq*4+0][br] = v.x*iv; sB[bq*4+1][br] = v.y*iv;
                sB[bq*4+2][br] = v.z*iv; sB[bq*4+3][br] = v.w*iv;
            }
            __syncthreads();
            #pragma unroll
            for (int k = 0; k < 32; k++){
                float a0 = sA[k][ty], a1 = sA[k][ty+16];
                float4 b0 = *(const float4*)&sB[k][tx*8];
                float4 b1 = *(const float4*)&sB[k][tx*8+4];
                float bb[8] = {b0.x,b0.y,b0.z,b0.w,b1.x,b1.y,b1.z,b1.w};
                #pragma unroll
                for (int j = 0; j < 8; j++){
                    acc[0][j] += a0*bb[j];
                    acc[1][j] += a1*bb[j];
                }
            }
            __syncthreads();
        }

        float* osim = (mat == 0) ? g_img_sim : g_txt_sim;
        #pragma unroll
        for (int i = 0; i < 2; i++){
            int lrow = ty + i*16;
            int row = r0 + lrow;
            float o[8];
            #pragma unroll
            for (int j = 0; j < 8; j++) o[j] = acc[i][j]*2.f;   // / TEMP
            float* dst = osim + ((size_t)(p*BB + row))*BB + tx*8;
            *(float4*)dst     = make_float4(o[0],o[1],o[2],o[3]);
            *(float4*)(dst+4) = make_float4(o[4],o[5],o[6],o[7]);
            uint32_t byte = 0;
            #pragma unroll
            for (int j = 0; j < 8; j++) if (o[j] > SIM_TH_F) byte |= (1u << j);
            atomicOr(&sbits[lrow*4 + (tx>>2)], byte << ((tx&3)*8));
        }
        __syncthreads();
        if (tid < 128)
            g_bits[mat][(p*BB + r0 + (tid>>2))*4 + (tid&3)] = sbits[tid];

    } else if (bid < NB_SIM + NB_POS){
        // ================= pos branch (2 rows per CTA) ========================
        const int pr = bid - NB_SIM;
        const int half = tid >> 7;
        const int wg = (tid >> 5) & 3;
        const int lane = tid & 31;
        const int row = pr*2 + half;           // == p*BB + b
        const int b = row & 127;
        const int p = row >> 7;
        __shared__ float s_e2[2][12];
        const float* f = feature + (size_t)row*DD;
        float fn2 = g_fn2[row];
        for (int k = wg; k < KKc; k += 4){
            int idx = cross_indices[b*KKc + k];
            const float* cc = centers + ((size_t)p*NN + idx)*DD;
            float dot = 0.f, sqv = 0.f;
            #pragma unroll
            for (int j = 0; j < 4; j++){
                float4 cf = *(const float4*)(cc + j*128 + lane*4);
                float4 ff = *(const float4*)(f  + j*128 + lane*4);
                dot += ff.x*cf.x + ff.y*cf.y + ff.z*cf.z + ff.w*cf.w;
                sqv += cf.x*cf.x + cf.y*cf.y + cf.z*cf.z + cf.w*cf.w;
            }
            dot = warpSum(dot);
            sqv = warpSum(sqv);
            if (lane == 0){
                float pd2 = fn2 + sqv - 2.f*dot;
                s_e2[half][k] = expf(-SCALE_F * sqrtf(fmaxf(pd2, 1e-12f)));
            }
        }
        __syncthreads();
        if ((tid & 127) == 0){
            float ssum = 0.f;
            #pragma unroll
            for (int k = 0; k < KKc; k++) ssum += s_e2[half][k];
            g_x[row] = logf(ssum);
        }
    } else {
        // ================= pos_vid gather branch ==============================
        int i = (bid - (NB_SIM + NB_POS))*256 + tid;
        if (i < BB*KKc && (3 + i) < out_size)
            out[3 + i] = (float)vid[cross_indices[i]];
    }
}

// ---------------- kl + neg-sum reduce per row ---------------------------------
__global__ void kl_kernel(){
    int p = blockIdx.x / BB, b = blockIdx.x % BB;
    int c = threadIdx.x;
    __shared__ unsigned char svv[128];

    // fold g_partial reduction for this row (deterministic tree order)
    float nsv = g_partial[((size_t)p*NT + c)*BB + b]
              + g_partial[((size_t)p*NT + 128 + c)*BB + b];
    float ns = blockSum128(nsv);
    if (c == 0) g_negsum[p*BB + b] = ns;

    const uint32_t* ib = &g_bits[0][(p*BB + c)*4];
    const uint32_t* tb = &g_bits[1][(p*BB + c)*4];
    uint32_t m = (ib[0]&tb[0]) | (ib[1]&tb[1]) | (ib[2]&tb[2]) | (ib[3]&tb[3]);
    int colm = (m != 0);
    svv[c] = (unsigned char)colm;
    float is = g_img_sim[((size_t)(p*BB+b))*BB + c];
    float ts = g_txt_sim[((size_t)(p*BB+b))*BB + c];
    float il = colm ? is : NEG_INF_F;
    float tl = colm ? ts : NEG_INF_F;
    float mi = blockMax128(il);
    float sumi = blockSum128(expf(il - mi));
    float lsei = mi + logf(sumi);
    float mt = blockMax128(tl);
    float sumt = blockSum128(expf(tl - mt));
    float lset = mt + logf(sumt);
    float img_logp = il - lsei;
    float txt_logp = tl - lset;
    float k1 = colm ? expf(txt_logp) * (txt_logp - img_logp) : 0.f;
    float k2 = colm ? expf(img_logp) * (img_logp - txt_logp) : 0.f;
    float s1 = blockSum128(k1);
    float s2 = blockSum128(k2);
    if (c == 0){
        int rv = svv[b];
        g_valid[p*BB+b] = rv;
        g_kl1[p*BB+b] = rv ? s1 : 0.f;
        g_kl2[p*BB+b] = rv ? s2 : 0.f;
    }
}

// ---------------- final combine: 512 threads, one per (p,b) -------------------
__global__ void final_kernel(float* __restrict__ out, int out_size){
    int tid = threadIdx.x;          // 0..511
    int p = tid >> 7;
    int row = tid;                  // == p*BB + b
    int w = (tid >> 5) & 3;         // warp-in-group
    int lane = tid & 31;

    __shared__ float rC[PP][4], rN[PP][4], r1[PP][4], r2[PP][4];
    __shared__ float resC[PP], resA[PP];

    float ns  = g_negsum[row];
    float xv  = g_x[row];
    float nvv = (float)g_valid[row];
    float k1v = g_kl1[row];
    float k2v = g_kl2[row];

    float v = logf(ns) - xv;
    float sC = warpSum(v);
    float sN = warpSum(nvv);
    float s1 = warpSum(k1v);
    float s2 = warpSum(k2v);
    if (lane == 0){
        rC[p][w] = sC; rN[p][w] = sN; r1[p][w] = s1; r2[p][w] = s2;
    }
    __syncthreads();
    if (tid < PP){
        float c4 = rC[tid][0]+rC[tid][1]+rC[tid][2]+rC[tid][3];
        float n4 = rN[tid][0]+rN[tid][1]+rN[tid][2]+rN[tid][3];
        float a4 = r1[tid][0]+r1[tid][1]+r1[tid][2]+r1[tid][3];
        float b4 = r2[tid][0]+r2[tid][1]+r2[tid][2]+r2[tid][3];
        float lp = c4 / (float)BB;
        if (isnan(lp)) lp = 0.f;
        resC[tid] = lp;
        float pq = 0.5f * (a4 + b4) / fmaxf(n4, 1.f);
        resA[tid] = (n4 > 0.f) ? pq : 0.f;
    }
    __syncthreads();
    if (tid == 0 && out_size >= 3){
        float closs = (resC[0]+resC[1]+resC[2]+resC[3]) / (float)PP;
        float aloss = resA[0]+resA[1]+resA[2]+resA[3];
        float klw = fmaxf(0.5f * (1.f - 1.f/60.f), 0.1f);
        out[0] = closs + klw * aloss;
        out[1] = closs;
        out[2] = aloss;
    }
}

// ---------------- launch ------------------------------------------------------
extern "C" void kernel_launch(void* const* d_in, const int* in_sizes, int n_in,
                              void* d_out, int out_size){
    const float* feature       = (const float*)d_in[0];
    const float* text_feature  = (const float*)d_in[1];
    const float* centers       = (const float*)d_in[2];
    const int*   position      = (const int*)d_in[3];
    const int*   cross_indices = (const int*)d_in[4];
    const int*   vid           = (const int*)d_in[5];
    float* out = (float*)d_out;

    static bool attr_set = false;
    if (!attr_set){
        cudaFuncSetAttribute(mega_kernel, cudaFuncAttributeMaxDynamicSharedMemorySize, NEG_SMEM);
        attr_set = true;
    }

    normalize_kernel<<<PP*BB, 128>>>(feature, text_feature);                       // idx 0
    mega_kernel<<<NB_TOTAL, 256, NEG_SMEM>>>(feature, text_feature, centers,
                                             cross_indices, position, vid,
                                             out, out_size);                       // idx 1
    kl_kernel<<<PP*BB, 128>>>();                                                   // idx 2
    final_kernel<<<1, 512>>>(out, out_size);                                       // idx 3
}

// round 17
// speedup vs baseline: 1.6982x; 1.0321x over previous
#include <cuda_runtime.h>
#include <cuda_bf16.h>
#include <cstdint>
#include <math.h>

#define PP 4
#define BB 128
#define DD 512
#define NN 32768
#define KKc 10
#define NT 256          // NN / 128 tiles
#define NEG_INF_F (-1e30f)
#define SIM_TH_F 0.7f
#define SCALE_F 10.0f

// mega grid layout: small work first (fills wave-1 slack), neg GEMM last
#define NB_SIM   32
#define NB_POS   256
#define NB_GATH  5
#define NB_SMALL (NB_SIM + NB_POS + NB_GATH)   // 293
#define NB_NEG   1024
#define NB_TOTAL (NB_SMALL + NB_NEG)           // 1317

// ---------------- scratch (device globals) -----------------------------------
__device__ float g_invI[PP*BB];
__device__ float g_invT[PP*BB];
__device__ float g_fn2[PP*BB];
__device__ float g_img_sim[PP*BB*BB];
__device__ float g_txt_sim[PP*BB*BB];
__device__ int   g_valid[PP*BB];
__device__ float g_kl1[PP*BB];
__device__ float g_kl2[PP*BB];
__device__ float g_x[PP*BB];
__device__ float g_negsum[PP*BB];
__device__ float g_partial[PP*NT*BB];
__device__ uint32_t g_bits[2][PP*BB*4];   // per-row 128-bit >TH bitmaps (img, txt)

// ---------------- warp helpers ------------------------------------------------
__device__ __forceinline__ float warpSum(float v){
    #pragma unroll
    for (int o=16;o;o>>=1) v += __shfl_xor_sync(0xffffffffu, v, o);
    return v;
}
__device__ __forceinline__ float warpMax(float v){
    #pragma unroll
    for (int o=16;o;o>>=1) v = fmaxf(v, __shfl_xor_sync(0xffffffffu, v, o));
    return v;
}
__device__ float blockSum128(float v){
    __shared__ float sh[4];
    int w = threadIdx.x>>5, l = threadIdx.x&31;
    v = warpSum(v);
    __syncthreads();
    if (l==0) sh[w] = v;
    __syncthreads();
    return sh[0]+sh[1]+sh[2]+sh[3];
}
__device__ float blockMax128(float v){
    __shared__ float sh[4];
    int w = threadIdx.x>>5, l = threadIdx.x&31;
    v = warpMax(v);
    __syncthreads();
    if (l==0) sh[w] = v;
    __syncthreads();
    return fmaxf(fmaxf(sh[0],sh[1]), fmaxf(sh[2],sh[3]));
}
__device__ __forceinline__ uint32_t smem_u32(const void* p){
    uint32_t a;
    asm("{ .reg .u64 t; cvta.to.shared.u64 t, %1; cvt.u32.u64 %0, t; }" : "=r"(a) : "l"(p));
    return a;
}
__device__ __forceinline__ void ldsm_x4(uint32_t* r, uint32_t addr){
    asm volatile("ldmatrix.sync.aligned.m8n8.x4.shared.b16 {%0,%1,%2,%3}, [%4];"
                 : "=r"(r[0]), "=r"(r[1]), "=r"(r[2]), "=r"(r[3]) : "r"(addr));
}
__device__ __forceinline__ void mma_tf32(float* c, const uint32_t* a, const uint32_t* b){
    asm volatile("mma.sync.aligned.m16n8k8.row.col.f32.tf32.tf32.f32 "
                 "{%0,%1,%2,%3}, {%4,%5,%6,%7}, {%8,%9}, {%0,%1,%2,%3};"
                 : "+f"(c[0]), "+f"(c[1]), "+f"(c[2]), "+f"(c[3])
                 : "r"(a[0]), "r"(a[1]), "r"(a[2]), "r"(a[3]), "r"(b[0]), "r"(b[1]));
}
__device__ __forceinline__ void cpasync16(uint32_t dst, const void* src){
    asm volatile("cp.async.cg.shared.global [%0], [%1], 16;" :: "r"(dst), "l"(src));
}
#define CP_COMMIT() asm volatile("cp.async.commit_group;" ::: "memory")
#define CP_WAIT2()  asm volatile("cp.async.wait_group 2;" ::: "memory")

// fast exp(-SCALE * sqrt(max(d, 1e-12))) via MUFU.RSQ (epilogue only)
__device__ __forceinline__ float negexp_dist(float d){
    float dm = fmaxf(d, 1e-12f);
    float dist = dm * rsqrtf(dm);
    return __expf(-SCALE_F * dist);
}

// ---------------- normalize: one warp per (p,b) row ---------------------------
// grid = 64 blocks x 256 threads (8 warps); warp w handles row blockIdx*8+w
__global__ __launch_bounds__(256) void normalize_kernel(const float* __restrict__ feature,
                                                        const float* __restrict__ text_feature){
    int wid = threadIdx.x >> 5, lane = threadIdx.x & 31;
    int row = blockIdx.x*8 + wid;           // == p*BB + b
    int p = row >> 7, b = row & 127;
    const float* f = feature + (size_t)row*DD;
    const float* t = text_feature + (size_t)(b*PP + p)*DD;
    float sf = 0.f, st = 0.f;
    #pragma unroll
    for (int j = 0; j < 4; j++){
        float4 v = *(const float4*)(f + j*128 + lane*4);
        sf += v.x*v.x + v.y*v.y + v.z*v.z + v.w*v.w;
        float4 w = *(const float4*)(t + j*128 + lane*4);
        st += w.x*w.x + w.y*w.y + w.z*w.z + w.w*w.w;
    }
    sf = warpSum(sf);
    st = warpSum(st);
    if (lane == 0){
        g_fn2[row]  = sf;
        g_invI[row] = 1.f / fmaxf(sqrtf(sf), 1e-12f);
        g_invT[row] = 1.f / fmaxf(sqrtf(st), 1e-12f);
    }
}

// ---------------- mega kernel: sim + pos + posvid + neg GEMM ------------------
// bid <  32          : sim GEMM 32x128 tile (img or txt) + threshold bitmaps
// bid in [32,288)    : pos term, 2 rows per CTA
// bid in [288,293)   : pos_vid gather -> out[3..]
// bid in [293,1317)  : neg tf32 HMMA tile (R12 internals; scheduled last)
#define TSTRIDE 80                // bytes per row (16 floats + 4 pad)
#define TMAT (BB*TSTRIDE)         // 10240 B per matrix per stage
#define TSTG (2*TMAT)             // A+B per stage = 20480
#define NSTAGE 4
#define OFF_CN2  (NSTAGE*TSTG)    // 81920
#define OFF_MASK (OFF_CN2 + 512)
#define OFF_RED  (OFF_MASK + 512)
#define NEG_SMEM (OFF_RED + 1024) // 83968 B

__device__ __forceinline__ void issue_chunk_f32(const float* __restrict__ Ab,
                                                const float* __restrict__ Bb,
                                                uint32_t stageBase, int k, int tid){
    #pragma unroll
    for (int j = 0; j < 4; j++){
        int idx = j*256 + tid;
        int r = (idx >> 2) & 127, q = idx & 3;
        bool isA = idx < 512;
        const float* src = isA ? Ab + (size_t)r*DD + k*16 + q*4
                               : Bb + (size_t)r*DD + k*16 + q*4;
        uint32_t dst = stageBase + (isA ? 0 : TMAT) + r*TSTRIDE + q*16;
        cpasync16(dst, src);
    }
}

__global__ __launch_bounds__(256, 2) void mega_kernel(const float* __restrict__ feature,
                                                      const float* __restrict__ text,
                                                      const float* __restrict__ centers,
                                                      const int* __restrict__ cross_indices,
                                                      const int* __restrict__ position,
                                                      const int* __restrict__ vid,
                                                      float* __restrict__ out, int out_size){
    extern __shared__ __align__(16) char dsm[];
    const int bid = blockIdx.x;
    const int tid = threadIdx.x;

    if (bid >= NB_SMALL){
        // ================= neg GEMM branch (R12 internals) ====================
        const int t2 = bid - NB_SMALL;
        const int p = t2 >> 8;
        const int tile = t2 & 255;
        const int n0g = tile * 128;
        const int wid = tid >> 5, lane = tid & 31;
        const int wm = wid >> 1, wn = wid & 1;

        float* s_cn2  = (float*)(dsm + OFF_CN2);
        float* s_mask = (float*)(dsm + OFF_MASK);
        float* s_red  = (float*)(dsm + OFF_RED);

        const float* Ab = feature + (size_t)p*BB*DD;
        const float* Bb = centers + ((size_t)p*NN + n0g)*DD;
        const uint32_t base = smem_u32(dsm);

        issue_chunk_f32(Ab, Bb, base + 0*TSTG, 0, tid); CP_COMMIT();
        issue_chunk_f32(Ab, Bb, base + 1*TSTG, 1, tid); CP_COMMIT();
        issue_chunk_f32(Ab, Bb, base + 2*TSTG, 2, tid); CP_COMMIT();

        if (tid < BB) s_mask[tid] = 1.f;
        __syncthreads();
        for (int i = tid; i < BB*KKc + BB; i += 256){
            int v = (i < BB*KKc) ? cross_indices[i] : position[i - BB*KKc];
            unsigned d = (unsigned)(v - n0g);
            if (d < 128u) s_mask[d] = 0.f;
        }

        float acc[2][8][4];
        #pragma unroll
        for (int i=0;i<2;i++)
            #pragma unroll
            for (int j=0;j<8;j++)
                #pragma unroll
                for (int e=0;e<4;e++) acc[i][j][e] = 0.f;

        const uint32_t aOff = (uint32_t)((((lane>>3)&1)*8 + (lane&7)) * TSTRIDE + (lane>>4)*16);
        const uint32_t bOff = (uint32_t)(((lane>>4)*8 + (lane&7)) * TSTRIDE + ((lane>>3)&1)*16);

        const int r0c = tid >> 1, hc = tid & 1;
        float sqAcc = 0.f;

        for (int c = 0; c < DD/16; c++){
            CP_WAIT2();
            __syncthreads();
            if (c + 3 < DD/16)
                issue_chunk_f32(Ab, Bb, base + ((c+3)&3)*TSTG, c+3, tid);
            CP_COMMIT();
            const uint32_t sAu = base + (c&3)*TSTG;
            const uint32_t sBu = sAu + TMAT;
            #pragma unroll
            for (int ks = 0; ks < 2; ks++){
                const uint32_t kb = ks*32;
                uint32_t a[2][4];
                #pragma unroll
                for (int i = 0; i < 2; i++)
                    ldsm_x4(a[i], sAu + (wm*32 + i*16)*TSTRIDE + aOff + kb);
                uint32_t b[4][4];
                #pragma unroll
                for (int j = 0; j < 4; j++)
                    ldsm_x4(b[j], sBu + (wn*64 + j*16)*TSTRIDE + bOff + kb);
                #pragma unroll
                for (int i = 0; i < 2; i++)
                    #pragma unroll
                    for (int j = 0; j < 4; j++){
                        mma_tf32(acc[i][j*2],   a[i], &b[j][0]);
                        mma_tf32(acc[i][j*2+1], a[i], &b[j][2]);
                    }
            }
            {
                const float* brow = (const float*)(dsm + (c&3)*TSTG + TMAT + r0c*TSTRIDE + hc*32);
                float4 v0 = *(const float4*)brow;
                float4 v1 = *(const float4*)(brow + 4);
                sqAcc += v0.x*v0.x + v0.y*v0.y + v0.z*v0.z + v0.w*v0.w
                       + v1.x*v1.x + v1.y*v1.y + v1.z*v1.z + v1.w*v1.w;
            }
        }
        {
            float sq = sqAcc + __shfl_xor_sync(0xffffffffu, sqAcc, 1);
            if (hc == 0) s_cn2[r0c] = sq;
        }
        __syncthreads();

        const int g = lane >> 2, tig = lane & 3;
        #pragma unroll
        for (int i = 0; i < 2; i++){
            int r0 = wm*32 + i*16 + g;
            int r1 = r0 + 8;
            float fn0 = g_fn2[p*BB + r0];
            float fn1 = g_fn2[p*BB + r1];
            float part0 = 0.f, part1 = 0.f;
            #pragma unroll
            for (int j = 0; j < 8; j++){
                int n = wn*64 + j*8 + tig*2;
                float mk0 = s_mask[n],   mk1 = s_mask[n+1];
                float cn0 = s_cn2[n],    cn1 = s_cn2[n+1];
                float d00 = fn0 + cn0 - 2.f*acc[i][j][0];
                float d01 = fn0 + cn1 - 2.f*acc[i][j][1];
                float d10 = fn1 + cn0 - 2.f*acc[i][j][2];
                float d11 = fn1 + cn1 - 2.f*acc[i][j][3];
                part0 += mk0*negexp_dist(d00) + mk1*negexp_dist(d01);
                part1 += mk0*negexp_dist(d10) + mk1*negexp_dist(d11);
            }
            part0 += __shfl_xor_sync(0xffffffffu, part0, 1);
            part0 += __shfl_xor_sync(0xffffffffu, part0, 2);
            part1 += __shfl_xor_sync(0xffffffffu, part1, 1);
            part1 += __shfl_xor_sync(0xffffffffu, part1, 2);
            if (tig == 0){
                s_red[r0*2 + wn] = part0;
                s_red[r1*2 + wn] = part1;
            }
        }
        __syncthreads();
        if (tid < BB)
            g_partial[((size_t)p*NT + tile)*BB + tid] = s_red[tid*2] + s_red[tid*2+1];

    } else if (bid < NB_SIM){
        // ================= sim GEMM branch ====================================
        const int s = bid;
        const int p = s >> 3, rt = (s >> 1) & 3, mat = s & 1;
        const int tx = tid & 15, ty = tid >> 4;
        float (*sA)[36]  = (float(*)[36])dsm;
        float (*sB)[132] = (float(*)[132])(dsm + 4608);
        uint32_t* sbits  = (uint32_t*)(dsm + 21504);
        const float* inv = (mat == 0) ? g_invI : g_invT;
        const int r0 = rt*32;

        if (tid < 128) sbits[tid] = 0;

        const int ar = tid >> 3, aq = tid & 7;
        const float invA = inv[p*BB + r0 + ar];
        const float* aPtr = (mat == 0)
            ? feature + (size_t)(p*BB + r0 + ar)*DD + aq*4
            : text    + (size_t)((r0 + ar)*PP + p)*DD + aq*4;
        float invB[4];
        const float* bPtr[4];
        #pragma unroll
        for (int it = 0; it < 4; it++){
            int idx = it*256 + tid;
            int br = idx >> 3, bq = idx & 7;
            invB[it] = inv[p*BB + br];
            bPtr[it] = (mat == 0)
                ? feature + (size_t)(p*BB + br)*DD + bq*4
                : text    + (size_t)(br*PP + p)*DD + bq*4;
        }

        float acc[2][8];
        #pragma unroll
        for (int i=0;i<2;i++)
            #pragma unroll
            for (int j=0;j<8;j++) acc[i][j] = 0.f;

        for (int k0 = 0; k0 < DD; k0 += 32){
            {
                float4 v = *(const float4*)(aPtr + k0);
                sA[aq*4+0][ar] = v.x*invA; sA[aq*4+1][ar] = v.y*invA;
                sA[aq*4+2][ar] = v.z*invA; sA[aq*4+3][ar] = v.w*invA;
            }
            #pragma unroll
            for (int it = 0; it < 4; it++){
                int idx = it*256 + tid;
                int br = idx >> 3, bq = idx & 7;
                float4 v = *(const float4*)(bPtr[it] + k0);
                float iv = invB[it];
                sB[bq*4+0][br] = v.x*iv; sB[bq*4+1][br] = v.y*iv;
                sB[bq*4+2][br] = v.z*iv; sB[bq*4+3][br] = v.w*iv;
            }
            __syncthreads();
            #pragma unroll
            for (int k = 0; k < 32; k++){
                float a0 = sA[k][ty], a1 = sA[k][ty+16];
                float4 b0 = *(const float4*)&sB[k][tx*8];
                float4 b1 = *(const float4*)&sB[k][tx*8+4];
                float bb[8] = {b0.x,b0.y,b0.z,b0.w,b1.x,b1.y,b1.z,b1.w};
                #pragma unroll
                for (int j = 0; j < 8; j++){
                    acc[0][j] += a0*bb[j];
                    acc[1][j] += a1*bb[j];
                }
            }
            __syncthreads();
        }

        float* osim = (mat == 0) ? g_img_sim : g_txt_sim;
        #pragma unroll
        for (int i = 0; i < 2; i++){
            int lrow = ty + i*16;
            int row = r0 + lrow;
            float o[8];
            #pragma unroll
            for (int j = 0; j < 8; j++) o[j] = acc[i][j]*2.f;   // / TEMP
            float* dst = osim + ((size_t)(p*BB + row))*BB + tx*8;
            *(float4*)dst     = make_float4(o[0],o[1],o[2],o[3]);
            *(float4*)(dst+4) = make_float4(o[4],o[5],o[6],o[7]);
            uint32_t byte = 0;
            #pragma unroll
            for (int j = 0; j < 8; j++) if (o[j] > SIM_TH_F) byte |= (1u << j);
            atomicOr(&sbits[lrow*4 + (tx>>2)], byte << ((tx&3)*8));
        }
        __syncthreads();
        if (tid < 128)
            g_bits[mat][(p*BB + r0 + (tid>>2))*4 + (tid&3)] = sbits[tid];

    } else if (bid < NB_SIM + NB_POS){
        // ================= pos branch (2 rows per CTA) ========================
        const int pr = bid - NB_SIM;
        const int half = tid >> 7;
        const int wg = (tid >> 5) & 3;
        const int lane = tid & 31;
        const int row = pr*2 + half;           // == p*BB + b
        const int b = row & 127;
        const int p = row >> 7;
        __shared__ float s_e2[2][12];
        const float* f = feature + (size_t)row*DD;
        float fn2 = g_fn2[row];
        for (int k = wg; k < KKc; k += 4){
            int idx = cross_indices[b*KKc + k];
            const float* cc = centers + ((size_t)p*NN + idx)*DD;
            float dot = 0.f, sqv = 0.f;
            #pragma unroll
            for (int j = 0; j < 4; j++){
                float4 cf = *(const float4*)(cc + j*128 + lane*4);
                float4 ff = *(const float4*)(f  + j*128 + lane*4);
                dot += ff.x*cf.x + ff.y*cf.y + ff.z*cf.z + ff.w*cf.w;
                sqv += cf.x*cf.x + cf.y*cf.y + cf.z*cf.z + cf.w*cf.w;
            }
            dot = warpSum(dot);
            sqv = warpSum(sqv);
            if (lane == 0){
                float pd2 = fn2 + sqv - 2.f*dot;
                s_e2[half][k] = expf(-SCALE_F * sqrtf(fmaxf(pd2, 1e-12f)));
            }
        }
        __syncthreads();
        if ((tid & 127) == 0){
            float ssum = 0.f;
            #pragma unroll
            for (int k = 0; k < KKc; k++) ssum += s_e2[half][k];
            g_x[row] = logf(ssum);
        }
    } else {
        // ================= pos_vid gather branch ==============================
        int i = (bid - (NB_SIM + NB_POS))*256 + tid;
        if (i < BB*KKc && (3 + i) < out_size)
            out[3 + i] = (float)vid[cross_indices[i]];
    }
}

// ---------------- kl + neg-sum reduce per row ---------------------------------
__global__ void kl_kernel(){
    int p = blockIdx.x / BB, b = blockIdx.x % BB;
    int c = threadIdx.x;
    __shared__ unsigned char svv[128];

    // fold g_partial reduction for this row (deterministic tree order)
    float nsv = g_partial[((size_t)p*NT + c)*BB + b]
              + g_partial[((size_t)p*NT + 128 + c)*BB + b];
    float ns = blockSum128(nsv);
    if (c == 0) g_negsum[p*BB + b] = ns;

    const uint32_t* ib = &g_bits[0][(p*BB + c)*4];
    const uint32_t* tb = &g_bits[1][(p*BB + c)*4];
    uint32_t m = (ib[0]&tb[0]) | (ib[1]&tb[1]) | (ib[2]&tb[2]) | (ib[3]&tb[3]);
    int colm = (m != 0);
    svv[c] = (unsigned char)colm;
    float is = g_img_sim[((size_t)(p*BB+b))*BB + c];
    float ts = g_txt_sim[((size_t)(p*BB+b))*BB + c];
    float il = colm ? is : NEG_INF_F;
    float tl = colm ? ts : NEG_INF_F;
    float mi = blockMax128(il);
    float sumi = blockSum128(expf(il - mi));
    float lsei = mi + logf(sumi);
    float mt = blockMax128(tl);
    float sumt = blockSum128(expf(tl - mt));
    float lset = mt + logf(sumt);
    float img_logp = il - lsei;
    float txt_logp = tl - lset;
    float k1 = colm ? expf(txt_logp) * (txt_logp - img_logp) : 0.f;
    float k2 = colm ? expf(img_logp) * (img_logp - txt_logp) : 0.f;
    float s1 = blockSum128(k1);
    float s2 = blockSum128(k2);
    if (c == 0){
        int rv = svv[b];
        g_valid[p*BB+b] = rv;
        g_kl1[p*BB+b] = rv ? s1 : 0.f;
        g_kl2[p*BB+b] = rv ? s2 : 0.f;
    }
}

// ---------------- final combine: 512 threads, one per (p,b) -------------------
__global__ void final_kernel(float* __restrict__ out, int out_size){
    int tid = threadIdx.x;          // 0..511
    int p = tid >> 7;
    int row = tid;                  // == p*BB + b
    int w = (tid >> 5) & 3;         // warp-in-group
    int lane = tid & 31;

    __shared__ float rC[PP][4], rN[PP][4], r1[PP][4], r2[PP][4];
    __shared__ float resC[PP], resA[PP];

    float ns  = g_negsum[row];
    float xv  = g_x[row];
    float nvv = (float)g_valid[row];
    float k1v = g_kl1[row];
    float k2v = g_kl2[row];

    float v = logf(ns) - xv;
    float sC = warpSum(v);
    float sN = warpSum(nvv);
    float s1 = warpSum(k1v);
    float s2 = warpSum(k2v);
    if (lane == 0){
        rC[p][w] = sC; rN[p][w] = sN; r1[p][w] = s1; r2[p][w] = s2;
    }
    __syncthreads();
    if (tid < PP){
        float c4 = rC[tid][0]+rC[tid][1]+rC[tid][2]+rC[tid][3];
        float n4 = rN[tid][0]+rN[tid][1]+rN[tid][2]+rN[tid][3];
        float a4 = r1[tid][0]+r1[tid][1]+r1[tid][2]+r1[tid][3];
        float b4 = r2[tid][0]+r2[tid][1]+r2[tid][2]+r2[tid][3];
        float lp = c4 / (float)BB;
        if (isnan(lp)) lp = 0.f;
        resC[tid] = lp;
        float pq = 0.5f * (a4 + b4) / fmaxf(n4, 1.f);
        resA[tid] = (n4 > 0.f) ? pq : 0.f;
    }
    __syncthreads();
    if (tid == 0 && out_size >= 3){
        float closs = (resC[0]+resC[1]+resC[2]+resC[3]) / (float)PP;
        float aloss = resA[0]+resA[1]+resA[2]+resA[3];
        float klw = fmaxf(0.5f * (1.f - 1.f/60.f), 0.1f);
        out[0] = closs + klw * aloss;
        out[1] = closs;
        out[2] = aloss;
    }
}

// ---------------- launch ------------------------------------------------------
extern "C" void kernel_launch(void* const* d_in, const int* in_sizes, int n_in,
                              void* d_out, int out_size){
    const float* feature       = (const float*)d_in[0];
    const float* text_feature  = (const float*)d_in[1];
    const float* centers       = (const float*)d_in[2];
    const int*   position      = (const int*)d_in[3];
    const int*   cross_indices = (const int*)d_in[4];
    const int*   vid           = (const int*)d_in[5];
    float* out = (float*)d_out;

    static bool attr_set = false;
    if (!attr_set){
        cudaFuncSetAttribute(mega_kernel, cudaFuncAttributeMaxDynamicSharedMemorySize, NEG_SMEM);
        attr_set = true;
    }

    normalize_kernel<<<PP*BB/8, 256>>>(feature, text_feature);                     // idx 0
    mega_kernel<<<NB_TOTAL, 256, NEG_SMEM>>>(feature, text_feature, centers,
                                             cross_indices, position, vid,
                                             out, out_size);                       // idx 1
    kl_kernel<<<PP*BB, 128>>>();                                                   // idx 2
    final_kernel<<<1, 512>>>(out, out_size);                                       // idx 3
}